// round 13
// baseline (speedup 1.0000x reference)
#include <cuda_runtime.h>
#include <cuda_bf16.h>
#include <math.h>

// CellularAutomatonDecoder via mma.sync m16n8k16 bf16 (base-target tensor cores).
// B=2048, T=32, D=128, V=256, 8 evolve steps.
// CTA = 128 rows (4 seqs x 32 pos), 512 threads / 16 warps (4 per SMSP for
// latency hiding). bf16 hi/lo split: 3 MMAs per logical GEMM, weight-tile-shared
// passes fused. Roll via ldmatrix A-row remapping. Weights double-buffered cp.async.

typedef unsigned int u32;

// ------------------------- global scratch -------------------------
__device__ __align__(16) __nv_bfloat16 g_w1t[12 * 16384]; // (j*4 + h*2 + hl)
__device__ __align__(16) __nv_bfloat16 g_w2t[ 4 * 16384]; // (h*2 + hl)
__device__ __align__(16) __nv_bfloat16 g_hdt[ 4 * 16384]; // (h*2 + hl)
__device__ float g_const_bias[256];
__device__ float g_alpha_sig;

// ------------------------- helpers -------------------------
__device__ __forceinline__ u32 smem_u32(const void* p){
    u32 a; asm("{ .reg .u64 t; cvta.to.shared.u64 t, %1; cvt.u32.u64 %0, t; }" : "=r"(a) : "l"(p));
    return a;
}
__device__ __forceinline__ void ldmx4(u32 addr, u32& r0, u32& r1, u32& r2, u32& r3){
    asm volatile("ldmatrix.sync.aligned.m8n8.x4.shared.b16 {%0,%1,%2,%3}, [%4];"
        : "=r"(r0), "=r"(r1), "=r"(r2), "=r"(r3) : "r"(addr));
}
__device__ __forceinline__ void hmma(float* d, u32 a0, u32 a1, u32 a2, u32 a3, u32 b0, u32 b1){
    asm volatile("mma.sync.aligned.m16n8k16.row.col.f32.bf16.bf16.f32 "
        "{%0,%1,%2,%3},{%4,%5,%6,%7},{%8,%9},{%0,%1,%2,%3};"
        : "+f"(d[0]), "+f"(d[1]), "+f"(d[2]), "+f"(d[3])
        : "r"(a0), "r"(a1), "r"(a2), "r"(a3), "r"(b0), "r"(b1));
}
// fast gelu/tanh (abs err <= ~2e-7; tolerance margin ~1e-4)
__device__ __forceinline__ float erf_appx(float x){
    const float ax = fabsf(x);
    const float t  = __fdividef(1.0f, fmaf(0.3275911f, ax, 1.0f));
    float p = fmaf(1.061405429f, t, -1.453152027f);
    p = fmaf(p, t, 1.421413741f);
    p = fmaf(p, t, -0.284496736f);
    p = fmaf(p, t, 0.254829592f);
    const float r = 1.0f - (p * t) * __expf(-ax * ax);
    return copysignf(r, x);
}
__device__ __forceinline__ float gelu_fast(float x){
    return 0.5f * x * (1.0f + erf_appx(x * 0.70710678118654752440f));
}
__device__ __forceinline__ float tanh_fast(float x){
    const float e = __expf(-2.0f * fabsf(x));
    const float r = __fdividef(1.0f - e, 1.0f + e);
    return copysignf(r, x);
}
__device__ __forceinline__ float gelu_exact(float x){
    return 0.5f * x * (1.0f + erff(x * 0.70710678118654752440f));
}
__device__ __forceinline__ __nv_bfloat162 split_hi2(float v0, float v1, __nv_bfloat162& lo){
    __nv_bfloat16 h0 = __float2bfloat16_rn(v0);
    __nv_bfloat16 h1 = __float2bfloat16_rn(v1);
    lo = __halves2bfloat162(__float2bfloat16_rn(v0 - __bfloat162float(h0)),
                            __float2bfloat16_rn(v1 - __bfloat162float(h1)));
    return __halves2bfloat162(h0, h1);
}

// Streamed-tile schedule. 132 tiles:
// t = step*16 + h*8 + v; v 0..5 = W1(j=v>>1, hl=v&1); v 6,7 = W2(hl=v-6).
// t >= 128: head (h*2 + hl).
__device__ __forceinline__ const __nv_bfloat16* tile_src(int t){
    if (t >= 132) t = 131;
    if (t < 128){
        const int u = t & 15, h = u >> 3, v = u & 7;
        if (v < 6){ const int j = v >> 1, hl = v & 1; return g_w1t + (j*4 + h*2 + hl)*16384; }
        return g_w2t + (h*2 + (v - 6))*16384;
    }
    return g_hdt + (t - 128)*16384;
}

// Warp tile: 64m x 16n (4 m16 tiles x 2 n8 tiles = 8 accumulators of 4).
// Fused dual-A pass: acc += A_hi@W + A_lo@W; B frags loaded once per k-step.
__device__ __forceinline__ void mma_pass2(u32 ahi, u32 dlo, u32 wbase, float (*acc)[4],
                                          int lane, int warpM, int warpN, int dj)
{
    u32 arow[4], brow;
    #pragma unroll
    for (int i = 0; i < 4; ++i){
        const int m = warpM*64 + i*16 + (lane & 15);
        const int mr = (m & 96) | ((m + dj) & 31);
        arow[i] = ahi + mr*272 + ((lane >> 4) << 4);
    }
    {
        const int n = warpN*16 + (((lane >> 4) & 1) << 3) + (lane & 7);
        brow = wbase + n*272 + (((lane >> 3) & 1) << 4);
    }
    #pragma unroll
    for (int ks = 0; ks < 8; ++ks){
        u32 b[2][2];
        ldmx4(brow + ks*32, b[0][0], b[0][1], b[1][0], b[1][1]);
        u32 a[4][4];
        #pragma unroll
        for (int i = 0; i < 4; ++i) ldmx4(arow[i] + ks*32, a[i][0], a[i][1], a[i][2], a[i][3]);
        #pragma unroll
        for (int i = 0; i < 4; ++i)
            #pragma unroll
            for (int j = 0; j < 2; ++j)
                hmma(acc[i*2+j], a[i][0], a[i][1], a[i][2], a[i][3], b[j][0], b[j][1]);
        #pragma unroll
        for (int i = 0; i < 4; ++i) ldmx4(arow[i] + dlo + ks*32, a[i][0], a[i][1], a[i][2], a[i][3]);
        #pragma unroll
        for (int i = 0; i < 4; ++i)
            #pragma unroll
            for (int j = 0; j < 2; ++j)
                hmma(acc[i*2+j], a[i][0], a[i][1], a[i][2], a[i][3], b[j][0], b[j][1]);
    }
}

// Single-A pass: acc += A@W.
__device__ __forceinline__ void mma_pass1(u32 abase, u32 wbase, float (*acc)[4],
                                          int lane, int warpM, int warpN, int dj)
{
    u32 arow[4], brow;
    #pragma unroll
    for (int i = 0; i < 4; ++i){
        const int m = warpM*64 + i*16 + (lane & 15);
        const int mr = (m & 96) | ((m + dj) & 31);
        arow[i] = abase + mr*272 + ((lane >> 4) << 4);
    }
    {
        const int n = warpN*16 + (((lane >> 4) & 1) << 3) + (lane & 7);
        brow = wbase + n*272 + (((lane >> 3) & 1) << 4);
    }
    #pragma unroll
    for (int ks = 0; ks < 8; ++ks){
        u32 b[2][2];
        ldmx4(brow + ks*32, b[0][0], b[0][1], b[1][0], b[1][1]);
        u32 a[4][4];
        #pragma unroll
        for (int i = 0; i < 4; ++i) ldmx4(arow[i] + ks*32, a[i][0], a[i][1], a[i][2], a[i][3]);
        #pragma unroll
        for (int i = 0; i < 4; ++i)
            #pragma unroll
            for (int j = 0; j < 2; ++j)
                hmma(acc[i*2+j], a[i][0], a[i][1], a[i][2], a[i][3], b[j][0], b[j][1]);
    }
}

// ------------------------- prep (const_bias, alpha) -------------------------
__global__ void __launch_bounds__(1024)
prep_kernel(const float* __restrict__ c_states,
            const float* __restrict__ Wc1,
            const float* __restrict__ bc1,
            const float* __restrict__ Wc2,
            const float* __restrict__ bc2,
            const float* __restrict__ W1,
            const float* __restrict__ b1,
            const float* __restrict__ alpha)
{
    __shared__ float cp[128];
    __shared__ float h1[256];
    __shared__ float rb[128];
    const int tid = threadIdx.x;
    if (tid < 128)
        cp[tid] = 0.25f * (c_states[tid] + c_states[128+tid] + c_states[256+tid] + c_states[384+tid]);
    __syncthreads();
    {
        const int n = tid >> 2, r = tid & 3;
        float s = 0.f;
        for (int d = r; d < 128; d += 4) s += cp[d] * __ldg(Wc1 + d*256 + n);
        s += __shfl_xor_sync(0xffffffffu, s, 1);
        s += __shfl_xor_sync(0xffffffffu, s, 2);
        if (r == 0) h1[n] = gelu_exact(s + bc1[n]);
    }
    __syncthreads();
    {
        const int n = tid >> 3, r = tid & 7;
        float s = 0.f;
        for (int k = r; k < 256; k += 8) s += h1[k] * __ldg(Wc2 + k*128 + n);
        s += __shfl_xor_sync(0xffffffffu, s, 1);
        s += __shfl_xor_sync(0xffffffffu, s, 2);
        s += __shfl_xor_sync(0xffffffffu, s, 4);
        if (r == 0) rb[n] = s + bc2[n];
    }
    __syncthreads();
    {
        const int n = tid >> 2, r = tid & 3;
        float s = 0.f;
        for (int d = r; d < 128; d += 4) s += rb[d] * __ldg(W1 + (384 + d)*256 + n);
        s += __shfl_xor_sync(0xffffffffu, s, 1);
        s += __shfl_xor_sync(0xffffffffu, s, 2);
        if (r == 0) g_const_bias[n] = s + b1[n];
    }
    if (tid == 0) g_alpha_sig = 1.0f / (1.0f + expf(-alpha[0]));
}

// ------------------------- pack weight tiles ([n][k] bf16 hi/lo) -------------
__global__ void pack_tiles(const float* __restrict__ W1,
                           const float* __restrict__ W2,
                           const float* __restrict__ head_w)
{
    const int idx = blockIdx.x * 256 + threadIdx.x;   // 0..327679
    const int t = idx >> 14;                           // 0..19
    const int e = idx & 16383;
    const int n = e >> 7, k = e & 127;
    float v; __nv_bfloat16* dst;
    if (t < 12) {                       // W1: t = j*4 + h*2 + hl
        const int j = t >> 2, h = (t >> 1) & 1;
        v = W1[(j*128 + k)*256 + h*128 + n];
        dst = g_w1t + t*16384 + e;
    } else if (t < 16) {                // W2: (t-12) = h*2 + hl
        const int u = t - 12, h = u >> 1;
        v = W2[(h*128 + k)*128 + n];
        dst = g_w2t + u*16384 + e;
    } else {                            // head: (t-16) = h*2 + hl
        const int u = t - 16, h = u >> 1;
        v = head_w[k*256 + h*128 + n];
        dst = g_hdt + u*16384 + e;
    }
    const __nv_bfloat16 hi = __float2bfloat16_rn(v);
    *dst = (t & 1) ? __float2bfloat16_rn(v - __bfloat162float(hi)) : hi;
}

// ------------------------- SMEM layout (bytes) -------------------------
// rows stride 272 B (128 bf16 + 16B pad) for all [128x128] bf16 tiles
#define OA_HI   0
#define OA_LO   34816
#define OH_HI   69632
#define OH_LO   104448
#define OW0     139264
#define OW1     174080
#define OCB     208896
#define OB2     209920
#define OLNG    210432
#define OLNB    210944
#define SMEM_TOTAL 211456
#define DLO_A   34816   /* OA_LO - OA_HI == OH_LO - OH_HI */

// ------------------------- main fused kernel (512 threads) -------------------
__global__ void __launch_bounds__(512, 1)
evolve_mma(const int*   __restrict__ tokens,
           const float* __restrict__ embed,
           const float* __restrict__ pos_embed,
           const float* __restrict__ b2,
           const float* __restrict__ ln_g,
           const float* __restrict__ ln_b,
           float*       __restrict__ out)
{
    extern __shared__ char smem[];
    const u32 sb  = smem_u32(smem);
    const int tid = threadIdx.x, lane = tid & 31, wid = tid >> 5;
    const int warpM = wid & 1, warpN = wid >> 1;   // 2 x 8 warp grid
    const int rowbase = blockIdx.x * 128;

    const u32 SA_HI = sb + OA_HI;
    const u32 SH_HI = sb + OH_HI;
    const u32 wb[2] = { sb + OW0, sb + OW1 };
    float* cb  = (float*)(smem + OCB);
    float* b2s = (float*)(smem + OB2);
    float* lng = (float*)(smem + OLNG);
    float* lnb = (float*)(smem + OLNB);

    if (tid < 256) cb[tid] = g_const_bias[tid];
    if (tid < 128) { b2s[tid] = b2[tid]; lng[tid] = ln_g[tid]; lnb[tid] = ln_b[tid]; }

    // ---- init cells = embed[token] + pos_embed (bf16 hi/lo split) ----
    {
        const int m = tid >> 2, kh = (tid & 3) * 32;
        const int g = rowbase + m;
        const int tok = __ldg(tokens + g);
        const float* e = embed + tok*128 + kh;
        const float* p = pos_embed + (m & 31)*128 + kh;
        char* hi = smem + OA_HI + m*272 + kh*2;
        char* lo = smem + OA_LO + m*272 + kh*2;
        #pragma unroll 4
        for (int q = 0; q < 32; q += 2) {
            __nv_bfloat162 l2;
            __nv_bfloat162 h2 = split_hi2(e[q] + p[q], e[q+1] + p[q+1], l2);
            *(__nv_bfloat162*)(hi + q*2) = h2;
            *(__nv_bfloat162*)(lo + q*2) = l2;
        }
    }

#define PREFETCH_TILE(srcp, sbuf) do { \
        const char* _g = (const char*)(srcp); const u32 _sb = (sbuf); \
        _Pragma("unroll") \
        for (int _i = 0; _i < 4; ++_i) { \
            const int _c = tid + _i*512; const int _row = _c >> 4, _seg = _c & 15; \
            asm volatile("cp.async.cg.shared.global [%0], [%1], 16;" :: \
                "r"(_sb + _row*272 + _seg*16), \
                "l"(__cvta_generic_to_global(_g + _c*16)) : "memory"); } \
        asm volatile("cp.async.commit_group;" ::: "memory"); \
    } while(0)
#define NEXT_TILE() do { \
        asm volatile("cp.async.wait_group 0;" ::: "memory"); \
        __syncthreads(); \
        if (tnext < 132) PREFETCH_TILE(tile_src(tnext), wb[pbuf ^ 1]); \
        ++tnext; cur = wb[pbuf]; pbuf ^= 1; \
    } while(0)

    int tnext = 1, pbuf = 0; u32 cur = wb[0];
    PREFETCH_TILE(tile_src(0), wb[0]);
    __syncthreads();   // cells + params visible

    const float aa = g_alpha_sig, om = 1.0f - aa;
    float acc2[8][4];

    // ================= 8 evolution steps =================
    for (int step = 0; step < 8; ++step) {
        #pragma unroll
        for (int x = 0; x < 8; ++x) { acc2[x][0]=0.f; acc2[x][1]=0.f; acc2[x][2]=0.f; acc2[x][3]=0.f; }

        for (int h = 0; h < 2; ++h) {
            float pre[8][4];
            #pragma unroll
            for (int x = 0; x < 8; ++x) { pre[x][0]=0.f; pre[x][1]=0.f; pre[x][2]=0.f; pre[x][3]=0.f; }

            // ---- matmul1: pre = X @ (W1c|W1l|W1r)[:, h-half], roll via A rows ----
            #pragma unroll 1
            for (int j = 0; j < 3; ++j) {
                const int dj = (j == 0) ? 0 : ((j == 1) ? 31 : 1);
                NEXT_TILE();   // W1(j,h) hi
                mma_pass2(SA_HI, DLO_A, cur, pre, lane, warpM, warpN, dj);
                NEXT_TILE();   // W1(j,h) lo
                mma_pass1(SA_HI, cur, pre, lane, warpM, warpN, dj);
            }
            // ---- epilogue1: H = gelu(pre + cb), split to bf16 hi/lo ----
            #pragma unroll
            for (int i = 0; i < 4; ++i) {
                #pragma unroll
                for (int j4 = 0; j4 < 2; ++j4) {
                    const int c = warpN*16 + j4*8 + (lane & 3)*2;
                    const float cb0 = cb[h*128 + c], cb1 = cb[h*128 + c + 1];
                    float* d = pre[i*2 + j4];
                    #pragma unroll
                    for (int rr = 0; rr < 2; ++rr) {
                        const int r = warpM*64 + i*16 + (lane >> 2) + rr*8;
                        __nv_bfloat162 l2;
                        __nv_bfloat162 h2 = split_hi2(gelu_fast(d[rr*2]   + cb0),
                                                      gelu_fast(d[rr*2+1] + cb1), l2);
                        *(__nv_bfloat162*)(smem + OH_HI + r*272 + c*2) = h2;
                        *(__nv_bfloat162*)(smem + OH_LO + r*272 + c*2) = l2;
                    }
                }
            }
            // ---- matmul2 partial: acc2 += H @ W2[h-chunk] ----
            NEXT_TILE();   // W2(h) hi   (sync publishes H)
            mma_pass2(SH_HI, DLO_A, cur, acc2, lane, warpM, warpN, 0);
            NEXT_TILE();   // W2(h) lo
            mma_pass1(SH_HI, cur, acc2, lane, warpM, warpN, 0);
        } // h

        // ---- epilogue2: cells = a*cells + (1-a)*tanh(acc2 + b2) ----
        #pragma unroll
        for (int i = 0; i < 4; ++i) {
            #pragma unroll
            for (int j4 = 0; j4 < 2; ++j4) {
                const int c = warpN*16 + j4*8 + (lane & 3)*2;
                const float bb0 = b2s[c], bb1 = b2s[c + 1];
                float* d = acc2[i*2 + j4];
                #pragma unroll
                for (int rr = 0; rr < 2; ++rr) {
                    const int r = warpM*64 + i*16 + (lane >> 2) + rr*8;
                    const u32 offs = r*272 + c*2;
                    __nv_bfloat162 oh = *(__nv_bfloat162*)(smem + OA_HI + offs);
                    __nv_bfloat162 ol = *(__nv_bfloat162*)(smem + OA_LO + offs);
                    const float o0 = __bfloat162float(oh.x) + __bfloat162float(ol.x);
                    const float o1 = __bfloat162float(oh.y) + __bfloat162float(ol.y);
                    const float v0 = aa*o0 + om*tanh_fast(d[rr*2]   + bb0);
                    const float v1 = aa*o1 + om*tanh_fast(d[rr*2+1] + bb1);
                    __nv_bfloat162 l2;
                    __nv_bfloat162 h2 = split_hi2(v0, v1, l2);
                    *(__nv_bfloat162*)(smem + OA_HI + offs) = h2;
                    *(__nv_bfloat162*)(smem + OA_LO + offs) = l2;
                }
            }
        }
    } // steps

    __syncthreads();
    // ============ LayerNorm per row (D=128), 4-way split-K, in-place ============
    {
        const int m = tid >> 2, part = tid & 3;   // 128 rows x 4 parts
        char* hi = smem + OA_HI + m*272;
        char* lo = smem + OA_LO + m*272;
        float s = 0.f, ss = 0.f;
        #pragma unroll 4
        for (int k = part*32; k < part*32 + 32; k += 2) {
            __nv_bfloat162 vh = *(__nv_bfloat162*)(hi + k*2);
            __nv_bfloat162 vl = *(__nv_bfloat162*)(lo + k*2);
            const float v0 = __bfloat162float(vh.x) + __bfloat162float(vl.x);
            const float v1 = __bfloat162float(vh.y) + __bfloat162float(vl.y);
            s += v0 + v1; ss += v0*v0 + v1*v1;
        }
        s  += __shfl_xor_sync(0xffffffffu, s, 1);
        s  += __shfl_xor_sync(0xffffffffu, s, 2);
        ss += __shfl_xor_sync(0xffffffffu, ss, 1);
        ss += __shfl_xor_sync(0xffffffffu, ss, 2);
        const float mu  = s * 0.0078125f;
        const float var = ss * 0.0078125f - mu*mu;
        const float inv = rsqrtf(var + 1e-5f);
        #pragma unroll 4
        for (int k = part*32; k < part*32 + 32; k += 2) {
            __nv_bfloat162 vh = *(__nv_bfloat162*)(hi + k*2);
            __nv_bfloat162 vl = *(__nv_bfloat162*)(lo + k*2);
            const float v0 = ((__bfloat162float(vh.x) + __bfloat162float(vl.x)) - mu)*inv*lng[k]   + lnb[k];
            const float v1 = ((__bfloat162float(vh.y) + __bfloat162float(vl.y)) - mu)*inv*lng[k+1] + lnb[k+1];
            __nv_bfloat162 l2;
            __nv_bfloat162 h2 = split_hi2(v0, v1, l2);
            *(__nv_bfloat162*)(hi + k*2) = h2;
            *(__nv_bfloat162*)(lo + k*2) = l2;
        }
    }

    // ================= head: out = cells @ head_w =================
    for (int h = 0; h < 2; ++h) {
        float hacc[8][4];
        #pragma unroll
        for (int x = 0; x < 8; ++x) { hacc[x][0]=0.f; hacc[x][1]=0.f; hacc[x][2]=0.f; hacc[x][3]=0.f; }
        NEXT_TILE();   // head(h) hi   (first call also publishes LN writes)
        mma_pass2(SA_HI, DLO_A, cur, hacc, lane, warpM, warpN, 0);
        NEXT_TILE();   // head(h) lo
        mma_pass1(SA_HI, cur, hacc, lane, warpM, warpN, 0);
        #pragma unroll
        for (int i = 0; i < 4; ++i) {
            #pragma unroll
            for (int j4 = 0; j4 < 2; ++j4) {
                const int c = warpN*16 + j4*8 + (lane & 3)*2;
                float* d = hacc[i*2 + j4];
                #pragma unroll
                for (int rr = 0; rr < 2; ++rr) {
                    const int r = warpM*64 + i*16 + (lane >> 2) + rr*8;
                    *(float2*)(out + (size_t)(rowbase + r)*256 + h*128 + c) =
                        make_float2(d[rr*2], d[rr*2+1]);
                }
            }
        }
    }
#undef PREFETCH_TILE
#undef NEXT_TILE
}

// ---------------------------------------------------------------------------
extern "C" void kernel_launch(void* const* d_in, const int* in_sizes, int n_in,
                              void* d_out, int out_size)
{
    const int*   tokens    = (const int*)  d_in[0];
    const float* c_states  = (const float*)d_in[1];
    const float* embed     = (const float*)d_in[2];
    const float* pos_embed = (const float*)d_in[3];
    const float* W1        = (const float*)d_in[4];
    const float* b1        = (const float*)d_in[5];
    const float* W2        = (const float*)d_in[6];
    const float* b2        = (const float*)d_in[7];
    const float* Wc1       = (const float*)d_in[8];
    const float* bc1       = (const float*)d_in[9];
    const float* Wc2       = (const float*)d_in[10];
    const float* bc2       = (const float*)d_in[11];
    const float* alpha     = (const float*)d_in[12];
    const float* ln_g      = (const float*)d_in[13];
    const float* ln_b      = (const float*)d_in[14];
    const float* head_w    = (const float*)d_in[15];
    float* out = (float*)d_out;

    cudaFuncSetAttribute(evolve_mma, cudaFuncAttributeMaxDynamicSharedMemorySize, SMEM_TOTAL);

    prep_kernel<<<1, 1024>>>(c_states, Wc1, bc1, Wc2, bc2, W1, b1, alpha);
    pack_tiles<<<1280, 256>>>(W1, W2, head_w);
    evolve_mma<<<512, 512, SMEM_TOTAL>>>(tokens, embed, pos_embed, b2, ln_g, ln_b, out);
}

// round 14
// speedup vs baseline: 1.2347x; 1.2347x over previous
#include <cuda_runtime.h>
#include <cuda_bf16.h>
#include <math.h>

// CellularAutomatonDecoder via mma.sync m16n8k16 bf16 (base-target tensor cores).
// B=2048, T=32, D=128, V=256, 8 evolve steps.
// R14: wave-balanced grid: 592 CTAs = 4 exact waves on 148 SMs.
//   blocks [0,444): ns=4 seqs (128 rows); [444,568): ns=2; [568,592): ns=1.
// bf16 hi/lo split: 3 MMAs per logical GEMM; roll via ldmatrix A-row remapping;
// weights double-buffered via cp.async from pre-packed [n][k] tile images.

typedef unsigned int u32;

// ------------------------- global scratch -------------------------
__device__ __align__(16) __nv_bfloat16 g_w1t[12 * 16384]; // (j*4 + h*2 + hl)
__device__ __align__(16) __nv_bfloat16 g_w2t[ 4 * 16384]; // (h*2 + hl)
__device__ __align__(16) __nv_bfloat16 g_hdt[ 4 * 16384]; // (h*2 + hl)
__device__ float g_const_bias[256];
__device__ float g_alpha_sig;

// ------------------------- helpers -------------------------
__device__ __forceinline__ u32 smem_u32(const void* p){
    u32 a; asm("{ .reg .u64 t; cvta.to.shared.u64 t, %1; cvt.u32.u64 %0, t; }" : "=r"(a) : "l"(p));
    return a;
}
__device__ __forceinline__ void ldmx4(u32 addr, u32& r0, u32& r1, u32& r2, u32& r3){
    asm volatile("ldmatrix.sync.aligned.m8n8.x4.shared.b16 {%0,%1,%2,%3}, [%4];"
        : "=r"(r0), "=r"(r1), "=r"(r2), "=r"(r3) : "r"(addr));
}
__device__ __forceinline__ void hmma(float* d, u32 a0, u32 a1, u32 a2, u32 a3, u32 b0, u32 b1){
    asm volatile("mma.sync.aligned.m16n8k16.row.col.f32.bf16.bf16.f32 "
        "{%0,%1,%2,%3},{%4,%5,%6,%7},{%8,%9},{%0,%1,%2,%3};"
        : "+f"(d[0]), "+f"(d[1]), "+f"(d[2]), "+f"(d[3])
        : "r"(a0), "r"(a1), "r"(a2), "r"(a3), "r"(b0), "r"(b1));
}
// fast gelu/tanh (abs err <= ~2e-7; tolerance margin ~1e-4)
__device__ __forceinline__ float erf_appx(float x){
    const float ax = fabsf(x);
    const float t  = __fdividef(1.0f, fmaf(0.3275911f, ax, 1.0f));
    float p = fmaf(1.061405429f, t, -1.453152027f);
    p = fmaf(p, t, 1.421413741f);
    p = fmaf(p, t, -0.284496736f);
    p = fmaf(p, t, 0.254829592f);
    const float r = 1.0f - (p * t) * __expf(-ax * ax);
    return copysignf(r, x);
}
__device__ __forceinline__ float gelu_fast(float x){
    return 0.5f * x * (1.0f + erf_appx(x * 0.70710678118654752440f));
}
__device__ __forceinline__ float tanh_fast(float x){
    const float e = __expf(-2.0f * fabsf(x));
    const float r = __fdividef(1.0f - e, 1.0f + e);
    return copysignf(r, x);
}
__device__ __forceinline__ float gelu_exact(float x){
    return 0.5f * x * (1.0f + erff(x * 0.70710678118654752440f));
}
__device__ __forceinline__ __nv_bfloat162 split_hi2(float v0, float v1, __nv_bfloat162& lo){
    __nv_bfloat16 h0 = __float2bfloat16_rn(v0);
    __nv_bfloat16 h1 = __float2bfloat16_rn(v1);
    lo = __halves2bfloat162(__float2bfloat16_rn(v0 - __bfloat162float(h0)),
                            __float2bfloat16_rn(v1 - __bfloat162float(h1)));
    return __halves2bfloat162(h0, h1);
}

// Streamed-tile schedule. 132 tiles:
// t = step*16 + h*8 + v; v 0..5 = W1(j=v>>1, hl=v&1); v 6,7 = W2(hl=v-6).
// t >= 128: head (h*2 + hl).
__device__ __forceinline__ const __nv_bfloat16* tile_src(int t){
    if (t >= 132) t = 131;
    if (t < 128){
        const int u = t & 15, h = u >> 3, v = u & 7;
        if (v < 6){ const int j = v >> 1, hl = v & 1; return g_w1t + (j*4 + h*2 + hl)*16384; }
        return g_w2t + (h*2 + (v - 6))*16384;
    }
    return g_hdt + (t - 128)*16384;
}

// Warp tile: (16*ns) m x 32 n. Fused dual-A pass: acc += A_hi@W + A_lo@W;
// B fragments loaded once per k-step. dj = roll within 32-row groups.
// ns is uniform per CTA; guards are warp-uniform (predication-cheap).
__device__ __forceinline__ void mma_pass2(u32 ahi, u32 dlo, u32 wbase, float (*acc)[4],
                                          int lane, int warpM, int warpN, int dj, int ns)
{
    u32 arow[4], brow4[2];
    #pragma unroll
    for (int i = 0; i < 4; ++i){
        const int m = warpM*(16*ns) + i*16 + (lane & 15);
        const int mr = (m & ~31) | ((m + dj) & 31);
        arow[i] = ahi + mr*272 + ((lane >> 4) << 4);
    }
    #pragma unroll
    for (int jp = 0; jp < 2; ++jp){
        const int n = warpN*32 + jp*16 + (((lane >> 4) & 1) << 3) + (lane & 7);
        brow4[jp] = wbase + n*272 + (((lane >> 3) & 1) << 4);
    }
    #pragma unroll
    for (int ks = 0; ks < 8; ++ks){
        u32 b[4][2];
        ldmx4(brow4[0] + ks*32, b[0][0], b[0][1], b[1][0], b[1][1]);
        ldmx4(brow4[1] + ks*32, b[2][0], b[2][1], b[3][0], b[3][1]);
        u32 a[4][4];
        #pragma unroll
        for (int i = 0; i < 4; ++i) if (i < ns) ldmx4(arow[i] + ks*32, a[i][0], a[i][1], a[i][2], a[i][3]);
        #pragma unroll
        for (int i = 0; i < 4; ++i) if (i < ns)
            #pragma unroll
            for (int j = 0; j < 4; ++j)
                hmma(acc[i*4+j], a[i][0], a[i][1], a[i][2], a[i][3], b[j][0], b[j][1]);
        #pragma unroll
        for (int i = 0; i < 4; ++i) if (i < ns) ldmx4(arow[i] + dlo + ks*32, a[i][0], a[i][1], a[i][2], a[i][3]);
        #pragma unroll
        for (int i = 0; i < 4; ++i) if (i < ns)
            #pragma unroll
            for (int j = 0; j < 4; ++j)
                hmma(acc[i*4+j], a[i][0], a[i][1], a[i][2], a[i][3], b[j][0], b[j][1]);
    }
}

// Single-A pass: acc += A@W.
__device__ __forceinline__ void mma_pass1(u32 abase, u32 wbase, float (*acc)[4],
                                          int lane, int warpM, int warpN, int dj, int ns)
{
    u32 arow[4], brow4[2];
    #pragma unroll
    for (int i = 0; i < 4; ++i){
        const int m = warpM*(16*ns) + i*16 + (lane & 15);
        const int mr = (m & ~31) | ((m + dj) & 31);
        arow[i] = abase + mr*272 + ((lane >> 4) << 4);
    }
    #pragma unroll
    for (int jp = 0; jp < 2; ++jp){
        const int n = warpN*32 + jp*16 + (((lane >> 4) & 1) << 3) + (lane & 7);
        brow4[jp] = wbase + n*272 + (((lane >> 3) & 1) << 4);
    }
    #pragma unroll
    for (int ks = 0; ks < 8; ++ks){
        u32 b[4][2];
        ldmx4(brow4[0] + ks*32, b[0][0], b[0][1], b[1][0], b[1][1]);
        ldmx4(brow4[1] + ks*32, b[2][0], b[2][1], b[3][0], b[3][1]);
        u32 a[4][4];
        #pragma unroll
        for (int i = 0; i < 4; ++i) if (i < ns) ldmx4(arow[i] + ks*32, a[i][0], a[i][1], a[i][2], a[i][3]);
        #pragma unroll
        for (int i = 0; i < 4; ++i) if (i < ns)
            #pragma unroll
            for (int j = 0; j < 4; ++j)
                hmma(acc[i*4+j], a[i][0], a[i][1], a[i][2], a[i][3], b[j][0], b[j][1]);
    }
}

// ------------------------- prep (const_bias, alpha) -------------------------
__global__ void __launch_bounds__(1024)
prep_kernel(const float* __restrict__ c_states,
            const float* __restrict__ Wc1,
            const float* __restrict__ bc1,
            const float* __restrict__ Wc2,
            const float* __restrict__ bc2,
            const float* __restrict__ W1,
            const float* __restrict__ b1,
            const float* __restrict__ alpha)
{
    __shared__ float cp[128];
    __shared__ float h1[256];
    __shared__ float rb[128];
    const int tid = threadIdx.x;
    if (tid < 128)
        cp[tid] = 0.25f * (c_states[tid] + c_states[128+tid] + c_states[256+tid] + c_states[384+tid]);
    __syncthreads();
    {
        const int n = tid >> 2, r = tid & 3;
        float s = 0.f;
        for (int d = r; d < 128; d += 4) s += cp[d] * __ldg(Wc1 + d*256 + n);
        s += __shfl_xor_sync(0xffffffffu, s, 1);
        s += __shfl_xor_sync(0xffffffffu, s, 2);
        if (r == 0) h1[n] = gelu_exact(s + bc1[n]);
    }
    __syncthreads();
    {
        const int n = tid >> 3, r = tid & 7;
        float s = 0.f;
        for (int k = r; k < 256; k += 8) s += h1[k] * __ldg(Wc2 + k*128 + n);
        s += __shfl_xor_sync(0xffffffffu, s, 1);
        s += __shfl_xor_sync(0xffffffffu, s, 2);
        s += __shfl_xor_sync(0xffffffffu, s, 4);
        if (r == 0) rb[n] = s + bc2[n];
    }
    __syncthreads();
    {
        const int n = tid >> 2, r = tid & 3;
        float s = 0.f;
        for (int d = r; d < 128; d += 4) s += rb[d] * __ldg(W1 + (384 + d)*256 + n);
        s += __shfl_xor_sync(0xffffffffu, s, 1);
        s += __shfl_xor_sync(0xffffffffu, s, 2);
        if (r == 0) g_const_bias[n] = s + b1[n];
    }
    if (tid == 0) g_alpha_sig = 1.0f / (1.0f + expf(-alpha[0]));
}

// ------------------------- pack weight tiles ([n][k] bf16 hi/lo) -------------
__global__ void pack_tiles(const float* __restrict__ W1,
                           const float* __restrict__ W2,
                           const float* __restrict__ head_w)
{
    const int idx = blockIdx.x * 256 + threadIdx.x;   // 0..327679
    const int t = idx >> 14;                           // 0..19
    const int e = idx & 16383;
    const int n = e >> 7, k = e & 127;
    float v; __nv_bfloat16* dst;
    if (t < 12) {                       // W1: t = j*4 + h*2 + hl
        const int j = t >> 2, h = (t >> 1) & 1;
        v = W1[(j*128 + k)*256 + h*128 + n];
        dst = g_w1t + t*16384 + e;
    } else if (t < 16) {                // W2: (t-12) = h*2 + hl
        const int u = t - 12, h = u >> 1;
        v = W2[(h*128 + k)*128 + n];
        dst = g_w2t + u*16384 + e;
    } else {                            // head: (t-16) = h*2 + hl
        const int u = t - 16, h = u >> 1;
        v = head_w[k*256 + h*128 + n];
        dst = g_hdt + u*16384 + e;
    }
    const __nv_bfloat16 hi = __float2bfloat16_rn(v);
    *dst = (t & 1) ? __float2bfloat16_rn(v - __bfloat162float(hi)) : hi;
}

// ------------------------- SMEM layout (bytes) -------------------------
// rows stride 272 B (128 bf16 + 16B pad) for all [<=128 x 128] bf16 tiles
#define OA_HI   0
#define OA_LO   34816
#define OH_HI   69632
#define OH_LO   104448
#define OW0     139264
#define OW1     174080
#define OCB     208896
#define OB2     209920
#define OLNG    210432
#define OLNB    210944
#define SMEM_TOTAL 211456
#define DLO_A   34816   /* OA_LO - OA_HI == OH_LO - OH_HI */

// ---------------- wave-balanced grid dispatch constants ----------------
#define N_FULL   444   /* blocks with ns=4: seqs 0..1775  (3 exact waves)   */
#define N_HALF   124   /* blocks with ns=2: seqs 1776..2023                  */
#define N_ONE     24   /* blocks with ns=1: seqs 2024..2047 (wave 4 = 148)  */
#define GRID_SZ  592

// ------------------------- main fused kernel (256 threads) -------------------
__global__ void __launch_bounds__(256, 1)
evolve_mma(const int*   __restrict__ tokens,
           const float* __restrict__ embed,
           const float* __restrict__ pos_embed,
           const float* __restrict__ b2,
           const float* __restrict__ ln_g,
           const float* __restrict__ ln_b,
           float*       __restrict__ out)
{
    extern __shared__ char smem[];
    const u32 sb  = smem_u32(smem);
    const int tid = threadIdx.x, lane = tid & 31, wid = tid >> 5;
    const int warpM = wid & 1, warpN = wid >> 1;   // 2 x 4 warp grid
    const int bid = blockIdx.x;

    // ---- wave-balanced dispatch ----
    int ns, seq0;
    if (bid < N_FULL)              { ns = 4; seq0 = bid * 4; }
    else if (bid < N_FULL + N_HALF){ ns = 2; seq0 = N_FULL*4 + (bid - N_FULL)*2; }
    else                           { ns = 1; seq0 = N_FULL*4 + N_HALF*2 + (bid - N_FULL - N_HALF); }
    const int rows = ns * 32;
    const int rowbase = seq0 * 32;

    const u32 SA_HI = sb + OA_HI;
    const u32 SH_HI = sb + OH_HI;
    const u32 wb[2] = { sb + OW0, sb + OW1 };
    float* cb  = (float*)(smem + OCB);
    float* b2s = (float*)(smem + OB2);
    float* lng = (float*)(smem + OLNG);
    float* lnb = (float*)(smem + OLNB);

    cb[tid] = g_const_bias[tid];
    if (tid < 128) { b2s[tid] = b2[tid]; lng[tid] = ln_g[tid]; lnb[tid] = ln_b[tid]; }

    // ---- init cells = embed[token] + pos_embed (bf16 hi/lo split) ----
    for (int idx = tid; idx < rows*2; idx += 256) {
        const int m = idx >> 1, kh = (idx & 1) * 64;
        const int g = rowbase + m;
        const int tok = __ldg(tokens + g);
        const float* e = embed + tok*128 + kh;
        const float* p = pos_embed + (m & 31)*128 + kh;
        char* hi = smem + OA_HI + m*272 + kh*2;
        char* lo = smem + OA_LO + m*272 + kh*2;
        #pragma unroll 8
        for (int q = 0; q < 64; q += 2) {
            __nv_bfloat162 l2;
            __nv_bfloat162 h2 = split_hi2(e[q] + p[q], e[q+1] + p[q+1], l2);
            *(__nv_bfloat162*)(hi + q*2) = h2;
            *(__nv_bfloat162*)(lo + q*2) = l2;
        }
    }

#define PREFETCH_TILE(srcp, sbuf) do { \
        const char* _g = (const char*)(srcp); const u32 _sb = (sbuf); \
        _Pragma("unroll") \
        for (int _i = 0; _i < 8; ++_i) { \
            const int _c = tid + _i*256; const int _row = _c >> 4, _seg = _c & 15; \
            asm volatile("cp.async.cg.shared.global [%0], [%1], 16;" :: \
                "r"(_sb + _row*272 + _seg*16), \
                "l"(__cvta_generic_to_global(_g + _c*16)) : "memory"); } \
        asm volatile("cp.async.commit_group;" ::: "memory"); \
    } while(0)
#define NEXT_TILE() do { \
        asm volatile("cp.async.wait_group 0;" ::: "memory"); \
        __syncthreads(); \
        if (tnext < 132) PREFETCH_TILE(tile_src(tnext), wb[pbuf ^ 1]); \
        ++tnext; cur = wb[pbuf]; pbuf ^= 1; \
    } while(0)

    int tnext = 1, pbuf = 0; u32 cur = wb[0];
    PREFETCH_TILE(tile_src(0), wb[0]);
    __syncthreads();   // cells + params visible

    const float aa = g_alpha_sig, om = 1.0f - aa;
    float acc2[16][4];

    // ================= 8 evolution steps =================
    for (int step = 0; step < 8; ++step) {
        #pragma unroll
        for (int x = 0; x < 16; ++x) { acc2[x][0]=0.f; acc2[x][1]=0.f; acc2[x][2]=0.f; acc2[x][3]=0.f; }

        for (int h = 0; h < 2; ++h) {
            float pre[16][4];
            #pragma unroll
            for (int x = 0; x < 16; ++x) { pre[x][0]=0.f; pre[x][1]=0.f; pre[x][2]=0.f; pre[x][3]=0.f; }

            // ---- matmul1: pre = X @ (W1c|W1l|W1r)[:, h-half], roll via A rows ----
            #pragma unroll 1
            for (int j = 0; j < 3; ++j) {
                const int dj = (j == 0) ? 0 : ((j == 1) ? 31 : 1);
                NEXT_TILE();   // W1(j,h) hi
                mma_pass2(SA_HI, DLO_A, cur, pre, lane, warpM, warpN, dj, ns);
                NEXT_TILE();   // W1(j,h) lo
                mma_pass1(SA_HI, cur, pre, lane, warpM, warpN, dj, ns);
            }
            // ---- epilogue1: H = gelu(pre + cb), split to bf16 hi/lo ----
            #pragma unroll
            for (int i = 0; i < 4; ++i) if (i < ns) {
                #pragma unroll
                for (int j4 = 0; j4 < 4; ++j4) {
                    const int c = warpN*32 + j4*8 + (lane & 3)*2;
                    const float cb0 = cb[h*128 + c], cb1 = cb[h*128 + c + 1];
                    float* d = pre[i*4 + j4];
                    #pragma unroll
                    for (int rr = 0; rr < 2; ++rr) {
                        const int r = warpM*(16*ns) + i*16 + (lane >> 2) + rr*8;
                        __nv_bfloat162 l2;
                        __nv_bfloat162 h2 = split_hi2(gelu_fast(d[rr*2]   + cb0),
                                                      gelu_fast(d[rr*2+1] + cb1), l2);
                        *(__nv_bfloat162*)(smem + OH_HI + r*272 + c*2) = h2;
                        *(__nv_bfloat162*)(smem + OH_LO + r*272 + c*2) = l2;
                    }
                }
            }
            // ---- matmul2 partial: acc2 += H @ W2[h-chunk] ----
            NEXT_TILE();   // W2(h) hi   (sync publishes H)
            mma_pass2(SH_HI, DLO_A, cur, acc2, lane, warpM, warpN, 0, ns);
            NEXT_TILE();   // W2(h) lo
            mma_pass1(SH_HI, cur, acc2, lane, warpM, warpN, 0, ns);
        } // h

        // ---- epilogue2: cells = a*cells + (1-a)*tanh(acc2 + b2) ----
        #pragma unroll
        for (int i = 0; i < 4; ++i) if (i < ns) {
            #pragma unroll
            for (int j4 = 0; j4 < 4; ++j4) {
                const int c = warpN*32 + j4*8 + (lane & 3)*2;
                const float bb0 = b2s[c], bb1 = b2s[c + 1];
                float* d = acc2[i*4 + j4];
                #pragma unroll
                for (int rr = 0; rr < 2; ++rr) {
                    const int r = warpM*(16*ns) + i*16 + (lane >> 2) + rr*8;
                    const u32 offs = r*272 + c*2;
                    __nv_bfloat162 oh = *(__nv_bfloat162*)(smem + OA_HI + offs);
                    __nv_bfloat162 ol = *(__nv_bfloat162*)(smem + OA_LO + offs);
                    const float o0 = __bfloat162float(oh.x) + __bfloat162float(ol.x);
                    const float o1 = __bfloat162float(oh.y) + __bfloat162float(ol.y);
                    const float v0 = aa*o0 + om*tanh_fast(d[rr*2]   + bb0);
                    const float v1 = aa*o1 + om*tanh_fast(d[rr*2+1] + bb1);
                    __nv_bfloat162 l2;
                    __nv_bfloat162 h2 = split_hi2(v0, v1, l2);
                    *(__nv_bfloat162*)(smem + OA_HI + offs) = h2;
                    *(__nv_bfloat162*)(smem + OA_LO + offs) = l2;
                }
            }
        }
    } // steps

    __syncthreads();
    // ================= LayerNorm per row (D=128), in-place =================
    if (tid < rows) {
        char* hi = smem + OA_HI + tid*272;
        char* lo = smem + OA_LO + tid*272;
        float s = 0.f, ss = 0.f;
        #pragma unroll 8
        for (int k = 0; k < 128; k += 2) {
            __nv_bfloat162 vh = *(__nv_bfloat162*)(hi + k*2);
            __nv_bfloat162 vl = *(__nv_bfloat162*)(lo + k*2);
            const float v0 = __bfloat162float(vh.x) + __bfloat162float(vl.x);
            const float v1 = __bfloat162float(vh.y) + __bfloat162float(vl.y);
            s += v0 + v1; ss += v0*v0 + v1*v1;
        }
        const float mu  = s * 0.0078125f;
        const float var = ss * 0.0078125f - mu*mu;
        const float inv = rsqrtf(var + 1e-5f);
        #pragma unroll 8
        for (int k = 0; k < 128; k += 2) {
            __nv_bfloat162 vh = *(__nv_bfloat162*)(hi + k*2);
            __nv_bfloat162 vl = *(__nv_bfloat162*)(lo + k*2);
            const float v0 = ((__bfloat162float(vh.x) + __bfloat162float(vl.x)) - mu)*inv*lng[k]   + lnb[k];
            const float v1 = ((__bfloat162float(vh.y) + __bfloat162float(vl.y)) - mu)*inv*lng[k+1] + lnb[k+1];
            __nv_bfloat162 l2;
            __nv_bfloat162 h2 = split_hi2(v0, v1, l2);
            *(__nv_bfloat162*)(hi + k*2) = h2;
            *(__nv_bfloat162*)(lo + k*2) = l2;
        }
    }

    // ================= head: out = cells @ head_w =================
    for (int h = 0; h < 2; ++h) {
        float hacc[16][4];
        #pragma unroll
        for (int x = 0; x < 16; ++x) { hacc[x][0]=0.f; hacc[x][1]=0.f; hacc[x][2]=0.f; hacc[x][3]=0.f; }
        NEXT_TILE();   // head(h) hi   (first call also publishes LN writes)
        mma_pass2(SA_HI, DLO_A, cur, hacc, lane, warpM, warpN, 0, ns);
        NEXT_TILE();   // head(h) lo
        mma_pass1(SA_HI, cur, hacc, lane, warpM, warpN, 0, ns);
        #pragma unroll
        for (int i = 0; i < 4; ++i) if (i < ns) {
            #pragma unroll
            for (int j4 = 0; j4 < 4; ++j4) {
                const int c = warpN*32 + j4*8 + (lane & 3)*2;
                float* d = hacc[i*4 + j4];
                #pragma unroll
                for (int rr = 0; rr < 2; ++rr) {
                    const int r = warpM*(16*ns) + i*16 + (lane >> 2) + rr*8;
                    *(float2*)(out + (size_t)(rowbase + r)*256 + h*128 + c) =
                        make_float2(d[rr*2], d[rr*2+1]);
                }
            }
        }
    }
#undef PREFETCH_TILE
#undef NEXT_TILE
}

// ---------------------------------------------------------------------------
extern "C" void kernel_launch(void* const* d_in, const int* in_sizes, int n_in,
                              void* d_out, int out_size)
{
    const int*   tokens    = (const int*)  d_in[0];
    const float* c_states  = (const float*)d_in[1];
    const float* embed     = (const float*)d_in[2];
    const float* pos_embed = (const float*)d_in[3];
    const float* W1        = (const float*)d_in[4];
    const float* b1        = (const float*)d_in[5];
    const float* W2        = (const float*)d_in[6];
    const float* b2        = (const float*)d_in[7];
    const float* Wc1       = (const float*)d_in[8];
    const float* bc1       = (const float*)d_in[9];
    const float* Wc2       = (const float*)d_in[10];
    const float* bc2       = (const float*)d_in[11];
    const float* alpha     = (const float*)d_in[12];
    const float* ln_g      = (const float*)d_in[13];
    const float* ln_b      = (const float*)d_in[14];
    const float* head_w    = (const float*)d_in[15];
    float* out = (float*)d_out;

    cudaFuncSetAttribute(evolve_mma, cudaFuncAttributeMaxDynamicSharedMemorySize, SMEM_TOTAL);

    prep_kernel<<<1, 1024>>>(c_states, Wc1, bc1, Wc2, bc2, W1, b1, alpha);
    pack_tiles<<<1280, 256>>>(W1, W2, head_w);
    evolve_mma<<<GRID_SZ, 256, SMEM_TOTAL>>>(tokens, embed, pos_embed, b2, ln_g, ln_b, out);
}

// round 15
// speedup vs baseline: 1.2731x; 1.0311x over previous
#include <cuda_runtime.h>
#include <cuda_bf16.h>
#include <math.h>

// CellularAutomatonDecoder via mma.sync m16n8k16 bf16 (base-target tensor cores).
// B=2048, T=32, D=128, V=256, 8 evolve steps.
// R15: weights fetched per-fragment via LDG.128 from gmem tiles pre-packed in
// mma B-fragment order (L2-resident, software-pipelined 1 k-group ahead,
// chained across passes). No cp.async, no weight smem, 5 barriers/step.
// acc2 stashed to smem between h-halves to cut register pressure.
// Wave-balanced grid: 592 CTAs = 4 exact waves on 148 SMs.

typedef unsigned int u32;

// ------------------------- global scratch -------------------------
// 20 tiles x 2048 uint4 (32KB each), fragment-ordered:
//   tile t: index ((nb*4 + kp)*32 + lane) -> uint4 {b0(ks=2kp), b1(2kp), b0(2kp+1), b1(2kp+1)}
//   where n = nb*8 + lane/4, k0 = kp*32 + (lane%4)*2.
// t: 0..11 = W1(j*4 + h*2 + hl); 12..15 = W2(h*2+hl); 16..19 = head(h*2+hl).
__device__ __align__(16) uint4 g_wfrag[20 * 2048];
__device__ float g_const_bias[256];
__device__ float g_alpha_sig;

// ------------------------- helpers -------------------------
__device__ __forceinline__ u32 smem_u32(const void* p){
    u32 a; asm("{ .reg .u64 t; cvta.to.shared.u64 t, %1; cvt.u32.u64 %0, t; }" : "=r"(a) : "l"(p));
    return a;
}
__device__ __forceinline__ void ldmx4(u32 addr, u32& r0, u32& r1, u32& r2, u32& r3){
    asm volatile("ldmatrix.sync.aligned.m8n8.x4.shared.b16 {%0,%1,%2,%3}, [%4];"
        : "=r"(r0), "=r"(r1), "=r"(r2), "=r"(r3) : "r"(addr));
}
__device__ __forceinline__ void hmma(float* d, u32 a0, u32 a1, u32 a2, u32 a3, u32 b0, u32 b1){
    asm volatile("mma.sync.aligned.m16n8k16.row.col.f32.bf16.bf16.f32 "
        "{%0,%1,%2,%3},{%4,%5,%6,%7},{%8,%9},{%0,%1,%2,%3};"
        : "+f"(d[0]), "+f"(d[1]), "+f"(d[2]), "+f"(d[3])
        : "r"(a0), "r"(a1), "r"(a2), "r"(a3), "r"(b0), "r"(b1));
}
// fast gelu/tanh (abs err <= ~2e-7; tolerance margin ~1e-4)
__device__ __forceinline__ float erf_appx(float x){
    const float ax = fabsf(x);
    const float t  = __fdividef(1.0f, fmaf(0.3275911f, ax, 1.0f));
    float p = fmaf(1.061405429f, t, -1.453152027f);
    p = fmaf(p, t, 1.421413741f);
    p = fmaf(p, t, -0.284496736f);
    p = fmaf(p, t, 0.254829592f);
    const float r = 1.0f - (p * t) * __expf(-ax * ax);
    return copysignf(r, x);
}
__device__ __forceinline__ float gelu_fast(float x){
    return 0.5f * x * (1.0f + erf_appx(x * 0.70710678118654752440f));
}
__device__ __forceinline__ float tanh_fast(float x){
    const float e = __expf(-2.0f * fabsf(x));
    const float r = __fdividef(1.0f - e, 1.0f + e);
    return copysignf(r, x);
}
__device__ __forceinline__ float gelu_exact(float x){
    return 0.5f * x * (1.0f + erff(x * 0.70710678118654752440f));
}
__device__ __forceinline__ __nv_bfloat162 split_hi2(float v0, float v1, __nv_bfloat162& lo){
    __nv_bfloat16 h0 = __float2bfloat16_rn(v0);
    __nv_bfloat16 h1 = __float2bfloat16_rn(v1);
    lo = __halves2bfloat162(__float2bfloat16_rn(v0 - __bfloat162float(h0)),
                            __float2bfloat16_rn(v1 - __bfloat162float(h1)));
    return __halves2bfloat162(h0, h1);
}

// Pass schedule (132 slots, same as R14):
// tc in [0,128): u = tc&15; h = u>>3; v = u&7; v<6 -> W1(j=v>>1, hl=v&1); else W2(hl=v-6).
// tc in [128,132): head (tc-128 = h*2+hl).
__device__ __forceinline__ const uint4* tile_ptr(int tc){
    if (tc >= 132) tc = 131;
    int t;
    if (tc < 128){
        const int u = tc & 15, h = u >> 3, v = u & 7;
        t = (v < 6) ? ((v >> 1)*4 + h*2 + (v & 1)) : (12 + h*2 + (v - 6));
    } else {
        t = 16 + (tc - 128);
    }
    return g_wfrag + t*2048;
}

// One [*,32n,128k] pass. NA=2: acc += A_hi@W + A_lo@W; NA=1: acc += A@W.
// B fragments LDG'd from fragment-ordered gmem, pipelined 1 k-group (k32) ahead;
// bq carries the preloaded fragments in/out across passes (wn = next tile).
template<int NA>
__device__ __forceinline__ void mma_passg(u32 abase, u32 dlo,
                                          const uint4* __restrict__ wt,
                                          const uint4* __restrict__ wn,
                                          uint4* bq, float (*acc)[4],
                                          int lane, int warpM, int warpN, int dj, int ns, int wofs)
{
    u32 arow[4];
    #pragma unroll
    for (int i = 0; i < 4; ++i){
        const int m = warpM*(16*ns) + i*16 + (lane & 15);
        const int mr = (m & ~31) | ((m + dj) & 31);
        arow[i] = abase + mr*272 + ((lane >> 4) << 4);
    }
    const uint4* wp = wt + wofs;
    const uint4* wq = wn + wofs;
    #pragma unroll
    for (int kp = 0; kp < 4; ++kp){
        uint4 bn[4];
        {
            const uint4* src = (kp < 3) ? (wp + (kp+1)*32) : wq;
            #pragma unroll
            for (int j = 0; j < 4; ++j) bn[j] = __ldg(src + j*128);
        }
        u32 a[4][4];
        // kstep even (k = kp*32 .. +15)
        #pragma unroll
        for (int i = 0; i < 4; ++i) if (i < ns) ldmx4(arow[i] + kp*64, a[i][0],a[i][1],a[i][2],a[i][3]);
        #pragma unroll
        for (int i = 0; i < 4; ++i) if (i < ns)
            #pragma unroll
            for (int j = 0; j < 4; ++j)
                hmma(acc[i*4+j], a[i][0],a[i][1],a[i][2],a[i][3], bq[j].x, bq[j].y);
        if (NA == 2){
            #pragma unroll
            for (int i = 0; i < 4; ++i) if (i < ns) ldmx4(arow[i] + dlo + kp*64, a[i][0],a[i][1],a[i][2],a[i][3]);
            #pragma unroll
            for (int i = 0; i < 4; ++i) if (i < ns)
                #pragma unroll
                for (int j = 0; j < 4; ++j)
                    hmma(acc[i*4+j], a[i][0],a[i][1],a[i][2],a[i][3], bq[j].x, bq[j].y);
        }
        // kstep odd (k = kp*32+16 .. +31)
        #pragma unroll
        for (int i = 0; i < 4; ++i) if (i < ns) ldmx4(arow[i] + kp*64 + 32, a[i][0],a[i][1],a[i][2],a[i][3]);
        #pragma unroll
        for (int i = 0; i < 4; ++i) if (i < ns)
            #pragma unroll
            for (int j = 0; j < 4; ++j)
                hmma(acc[i*4+j], a[i][0],a[i][1],a[i][2],a[i][3], bq[j].z, bq[j].w);
        if (NA == 2){
            #pragma unroll
            for (int i = 0; i < 4; ++i) if (i < ns) ldmx4(arow[i] + dlo + kp*64 + 32, a[i][0],a[i][1],a[i][2],a[i][3]);
            #pragma unroll
            for (int i = 0; i < 4; ++i) if (i < ns)
                #pragma unroll
                for (int j = 0; j < 4; ++j)
                    hmma(acc[i*4+j], a[i][0],a[i][1],a[i][2],a[i][3], bq[j].z, bq[j].w);
        }
        #pragma unroll
        for (int j = 0; j < 4; ++j) bq[j] = bn[j];
    }
}

// ------------------------- prep (const_bias, alpha) -------------------------
__global__ void __launch_bounds__(1024)
prep_kernel(const float* __restrict__ c_states,
            const float* __restrict__ Wc1,
            const float* __restrict__ bc1,
            const float* __restrict__ Wc2,
            const float* __restrict__ bc2,
            const float* __restrict__ W1,
            const float* __restrict__ b1,
            const float* __restrict__ alpha)
{
    __shared__ float cp[128];
    __shared__ float h1[256];
    __shared__ float rb[128];
    const int tid = threadIdx.x;
    if (tid < 128)
        cp[tid] = 0.25f * (c_states[tid] + c_states[128+tid] + c_states[256+tid] + c_states[384+tid]);
    __syncthreads();
    {
        const int n = tid >> 2, r = tid & 3;
        float s = 0.f;
        for (int d = r; d < 128; d += 4) s += cp[d] * __ldg(Wc1 + d*256 + n);
        s += __shfl_xor_sync(0xffffffffu, s, 1);
        s += __shfl_xor_sync(0xffffffffu, s, 2);
        if (r == 0) h1[n] = gelu_exact(s + bc1[n]);
    }
    __syncthreads();
    {
        const int n = tid >> 3, r = tid & 7;
        float s = 0.f;
        for (int k = r; k < 256; k += 8) s += h1[k] * __ldg(Wc2 + k*128 + n);
        s += __shfl_xor_sync(0xffffffffu, s, 1);
        s += __shfl_xor_sync(0xffffffffu, s, 2);
        s += __shfl_xor_sync(0xffffffffu, s, 4);
        if (r == 0) rb[n] = s + bc2[n];
    }
    __syncthreads();
    {
        const int n = tid >> 2, r = tid & 3;
        float s = 0.f;
        for (int d = r; d < 128; d += 4) s += rb[d] * __ldg(W1 + (384 + d)*256 + n);
        s += __shfl_xor_sync(0xffffffffu, s, 1);
        s += __shfl_xor_sync(0xffffffffu, s, 2);
        if (r == 0) g_const_bias[n] = s + b1[n];
    }
    if (tid == 0) g_alpha_sig = 1.0f / (1.0f + expf(-alpha[0]));
}

// ------------------ pack weights into mma B-fragment order ------------------
// 40960 chunks = 20 tiles x 2048; each thread writes one uint4.
__global__ void pack_frag(const float* __restrict__ W1,
                          const float* __restrict__ W2,
                          const float* __restrict__ head_w)
{
    const int idx = blockIdx.x * 256 + threadIdx.x;   // 0..40959
    const int t = idx >> 11;
    const int c = idx & 2047;
    const int nb = c >> 7, kp = (c >> 5) & 3, lane = c & 31;
    const int n  = nb*8 + (lane >> 2);
    const int k0 = kp*32 + (lane & 3)*2;
    const int hl = t & 1;

    float v[8];
    #pragma unroll
    for (int q = 0; q < 4; ++q) {
        const int k = k0 + q*8;      // k, k+1
        float a, b;
        if (t < 12) {
            const int j = t >> 2, h = (t >> 1) & 1;
            a = W1[(j*128 + k  )*256 + h*128 + n];
            b = W1[(j*128 + k+1)*256 + h*128 + n];
        } else if (t < 16) {
            const int h = (t - 12) >> 1;
            a = W2[(h*128 + k  )*128 + n];
            b = W2[(h*128 + k+1)*128 + n];
        } else {
            const int h = (t - 16) >> 1;
            a = head_w[(k  )*256 + h*128 + n];
            b = head_w[(k+1)*256 + h*128 + n];
        }
        v[q*2]   = a;
        v[q*2+1] = b;
    }
    u32 u[4];
    #pragma unroll
    for (int q = 0; q < 4; ++q) {
        __nv_bfloat16 h0 = __float2bfloat16_rn(v[q*2]);
        __nv_bfloat16 h1 = __float2bfloat16_rn(v[q*2+1]);
        __nv_bfloat16 e0 = hl ? __float2bfloat16_rn(v[q*2]   - __bfloat162float(h0)) : h0;
        __nv_bfloat16 e1 = hl ? __float2bfloat16_rn(v[q*2+1] - __bfloat162float(h1)) : h1;
        __nv_bfloat162 p = __halves2bfloat162(e0, e1);
        u[q] = *(u32*)&p;
    }
    g_wfrag[idx] = make_uint4(u[0], u[1], u[2], u[3]);
}

// ------------------------- SMEM layout (bytes) -------------------------
// A/H tiles: rows stride 272 B (128 bf16 + 16B pad)
#define OA_HI   0
#define OA_LO   34816
#define OH_HI   69632
#define OH_LO   104448
#define OCB     139264
#define OB2     140288
#define OLNG    140800
#define OLNB    141312
#define OSTASH  141824      /* 16 x 256 float4 = 64KB acc2 stash */
#define SMEM_TOTAL 207360
#define DLO_A   34816

// ---------------- wave-balanced grid dispatch constants ----------------
#define N_FULL   444
#define N_HALF   124
#define GRID_SZ  592

// ------------------------- main fused kernel (256 threads) -------------------
__global__ void __launch_bounds__(256, 1)
evolve_mma(const int*   __restrict__ tokens,
           const float* __restrict__ embed,
           const float* __restrict__ pos_embed,
           const float* __restrict__ b2,
           const float* __restrict__ ln_g,
           const float* __restrict__ ln_b,
           float*       __restrict__ out)
{
    extern __shared__ char smem[];
    const u32 sb  = smem_u32(smem);
    const int tid = threadIdx.x, lane = tid & 31, wid = tid >> 5;
    const int warpM = wid & 1, warpN = wid >> 1;   // 2 x 4 warp grid
    const int bid = blockIdx.x;

    // ---- wave-balanced dispatch ----
    int ns, seq0;
    if (bid < N_FULL)              { ns = 4; seq0 = bid * 4; }
    else if (bid < N_FULL + N_HALF){ ns = 2; seq0 = N_FULL*4 + (bid - N_FULL)*2; }
    else                           { ns = 1; seq0 = N_FULL*4 + N_HALF*2 + (bid - N_FULL - N_HALF); }
    const int rows = ns * 32;
    const int rowbase = seq0 * 32;

    const u32 SA_HI = sb + OA_HI;
    const u32 SH_HI = sb + OH_HI;
    float*  cb    = (float*)(smem + OCB);
    float*  b2s   = (float*)(smem + OB2);
    float*  lng   = (float*)(smem + OLNG);
    float*  lnb   = (float*)(smem + OLNB);
    float4* stash = (float4*)(smem + OSTASH);

    cb[tid] = g_const_bias[tid];
    if (tid < 128) { b2s[tid] = b2[tid]; lng[tid] = ln_g[tid]; lnb[tid] = ln_b[tid]; }

    // ---- init cells = embed[token] + pos_embed (bf16 hi/lo split) ----
    for (int idx = tid; idx < rows*2; idx += 256) {
        const int m = idx >> 1, kh = (idx & 1) * 64;
        const int g = rowbase + m;
        const int tok = __ldg(tokens + g);
        const float* e = embed + tok*128 + kh;
        const float* p = pos_embed + (m & 31)*128 + kh;
        char* hi = smem + OA_HI + m*272 + kh*2;
        char* lo = smem + OA_LO + m*272 + kh*2;
        #pragma unroll 8
        for (int q = 0; q < 64; q += 2) {
            __nv_bfloat162 l2;
            __nv_bfloat162 h2 = split_hi2(e[q] + p[q], e[q+1] + p[q+1], l2);
            *(__nv_bfloat162*)(hi + q*2) = h2;
            *(__nv_bfloat162*)(lo + q*2) = l2;
        }
    }

    const int wofs = warpN*512 + lane;   // uint4 units: (nb=warpN*4+j) stride 128, kp stride 32
    int tc = 0;
    uint4 bq[4];
    {
        const uint4* w0 = tile_ptr(0) + wofs;
        #pragma unroll
        for (int j = 0; j < 4; ++j) bq[j] = __ldg(w0 + j*128);
    }
    __syncthreads();   // cells + params visible

#define PASS(NA, ABASE, DJ, ACC) do { \
        mma_passg<NA>(ABASE, DLO_A, tile_ptr(tc), tile_ptr(tc+1), bq, ACC, \
                      lane, warpM, warpN, DJ, ns, wofs); ++tc; } while(0)

    const float aa = g_alpha_sig, om = 1.0f - aa;

    // ================= 8 evolution steps =================
    for (int step = 0; step < 8; ++step) {
        for (int h = 0; h < 2; ++h) {
            float pre[16][4];
            #pragma unroll
            for (int x = 0; x < 16; ++x) { pre[x][0]=0.f; pre[x][1]=0.f; pre[x][2]=0.f; pre[x][3]=0.f; }

            // ---- matmul1: pre = X @ (W1c|W1l|W1r)[:, h-half], roll via A rows ----
            #pragma unroll 1
            for (int j = 0; j < 3; ++j) {
                const int dj = (j == 0) ? 0 : ((j == 1) ? 31 : 1);
                PASS(2, SA_HI, dj, pre);   // W1(j,h) hi x (A_hi + A_lo)
                PASS(1, SA_HI, dj, pre);   // W1(j,h) lo x A_hi
            }
            __syncthreads();   // all warps done reading H (previous matmul2)
            // ---- epilogue1: H = gelu(pre + cb), split to bf16 hi/lo ----
            #pragma unroll
            for (int i = 0; i < 4; ++i) if (i < ns) {
                #pragma unroll
                for (int j4 = 0; j4 < 4; ++j4) {
                    const int c = warpN*32 + j4*8 + (lane & 3)*2;
                    const float cb0 = cb[h*128 + c], cb1 = cb[h*128 + c + 1];
                    float* d = pre[i*4 + j4];
                    #pragma unroll
                    for (int rr = 0; rr < 2; ++rr) {
                        const int r = warpM*(16*ns) + i*16 + (lane >> 2) + rr*8;
                        __nv_bfloat162 l2;
                        __nv_bfloat162 h2 = split_hi2(gelu_fast(d[rr*2]   + cb0),
                                                      gelu_fast(d[rr*2+1] + cb1), l2);
                        *(__nv_bfloat162*)(smem + OH_HI + r*272 + c*2) = h2;
                        *(__nv_bfloat162*)(smem + OH_LO + r*272 + c*2) = l2;
                    }
                }
            }
            __syncthreads();   // H published

            // ---- matmul2: acc2 (+)= H @ W2[h-chunk]; stash between halves ----
            float acc2[16][4];
            if (h == 0) {
                #pragma unroll
                for (int x = 0; x < 16; ++x) { acc2[x][0]=0.f; acc2[x][1]=0.f; acc2[x][2]=0.f; acc2[x][3]=0.f; }
            } else {
                #pragma unroll
                for (int x = 0; x < 16; ++x) {
                    float4 v = stash[(x << 8) | tid];
                    acc2[x][0]=v.x; acc2[x][1]=v.y; acc2[x][2]=v.z; acc2[x][3]=v.w;
                }
            }
            PASS(2, SH_HI, 0, acc2);   // W2(h) hi x (H_hi + H_lo)
            PASS(1, SH_HI, 0, acc2);   // W2(h) lo x H_hi

            if (h == 0) {
                #pragma unroll
                for (int x = 0; x < 16; ++x)
                    stash[(x << 8) | tid] = make_float4(acc2[x][0], acc2[x][1], acc2[x][2], acc2[x][3]);
            } else {
                // ---- epilogue2: cells = a*cells + (1-a)*tanh(acc2 + b2) ----
                #pragma unroll
                for (int i = 0; i < 4; ++i) if (i < ns) {
                    #pragma unroll
                    for (int j4 = 0; j4 < 4; ++j4) {
                        const int c = warpN*32 + j4*8 + (lane & 3)*2;
                        const float bb0 = b2s[c], bb1 = b2s[c + 1];
                        float* d = acc2[i*4 + j4];
                        #pragma unroll
                        for (int rr = 0; rr < 2; ++rr) {
                            const int r = warpM*(16*ns) + i*16 + (lane >> 2) + rr*8;
                            const u32 offs = r*272 + c*2;
                            __nv_bfloat162 oh = *(__nv_bfloat162*)(smem + OA_HI + offs);
                            __nv_bfloat162 ol = *(__nv_bfloat162*)(smem + OA_LO + offs);
                            const float o0 = __bfloat162float(oh.x) + __bfloat162float(ol.x);
                            const float o1 = __bfloat162float(oh.y) + __bfloat162float(ol.y);
                            const float v0 = aa*o0 + om*tanh_fast(d[rr*2]   + bb0);
                            const float v1 = aa*o1 + om*tanh_fast(d[rr*2+1] + bb1);
                            __nv_bfloat162 l2;
                            __nv_bfloat162 h2 = split_hi2(v0, v1, l2);
                            *(__nv_bfloat162*)(smem + OA_HI + offs) = h2;
                            *(__nv_bfloat162*)(smem + OA_LO + offs) = l2;
                        }
                    }
                }
            }
        } // h
        __syncthreads();   // A updates published for next step
    } // steps

    // ================= LayerNorm per row (D=128), in-place =================
    if (tid < rows) {
        char* hi = smem + OA_HI + tid*272;
        char* lo = smem + OA_LO + tid*272;
        float s = 0.f, ss = 0.f;
        #pragma unroll 8
        for (int k = 0; k < 128; k += 2) {
            __nv_bfloat162 vh = *(__nv_bfloat162*)(hi + k*2);
            __nv_bfloat162 vl = *(__nv_bfloat162*)(lo + k*2);
            const float v0 = __bfloat162float(vh.x) + __bfloat162float(vl.x);
            const float v1 = __bfloat162float(vh.y) + __bfloat162float(vl.y);
            s += v0 + v1; ss += v0*v0 + v1*v1;
        }
        const float mu  = s * 0.0078125f;
        const float var = ss * 0.0078125f - mu*mu;
        const float inv = rsqrtf(var + 1e-5f);
        #pragma unroll 8
        for (int k = 0; k < 128; k += 2) {
            __nv_bfloat162 vh = *(__nv_bfloat162*)(hi + k*2);
            __nv_bfloat162 vl = *(__nv_bfloat162*)(lo + k*2);
            const float v0 = ((__bfloat162float(vh.x) + __bfloat162float(vl.x)) - mu)*inv*lng[k]   + lnb[k];
            const float v1 = ((__bfloat162float(vh.y) + __bfloat162float(vl.y)) - mu)*inv*lng[k+1] + lnb[k+1];
            __nv_bfloat162 l2;
            __nv_bfloat162 h2 = split_hi2(v0, v1, l2);
            *(__nv_bfloat162*)(hi + k*2) = h2;
            *(__nv_bfloat162*)(lo + k*2) = l2;
        }
    }
    __syncthreads();   // LN results published

    // ================= head: out = cells @ head_w =================
    for (int h = 0; h < 2; ++h) {
        float hacc[16][4];
        #pragma unroll
        for (int x = 0; x < 16; ++x) { hacc[x][0]=0.f; hacc[x][1]=0.f; hacc[x][2]=0.f; hacc[x][3]=0.f; }
        PASS(2, SA_HI, 0, hacc);
        PASS(1, SA_HI, 0, hacc);
        #pragma unroll
        for (int i = 0; i < 4; ++i) if (i < ns) {
            #pragma unroll
            for (int j4 = 0; j4 < 4; ++j4) {
                const int c = warpN*32 + j4*8 + (lane & 3)*2;
                float* d = hacc[i*4 + j4];
                #pragma unroll
                for (int rr = 0; rr < 2; ++rr) {
                    const int r = warpM*(16*ns) + i*16 + (lane >> 2) + rr*8;
                    *(float2*)(out + (size_t)(rowbase + r)*256 + h*128 + c) =
                        make_float2(d[rr*2], d[rr*2+1]);
                }
            }
        }
    }
#undef PASS
}

// ---------------------------------------------------------------------------
extern "C" void kernel_launch(void* const* d_in, const int* in_sizes, int n_in,
                              void* d_out, int out_size)
{
    const int*   tokens    = (const int*)  d_in[0];
    const float* c_states  = (const float*)d_in[1];
    const float* embed     = (const float*)d_in[2];
    const float* pos_embed = (const float*)d_in[3];
    const float* W1        = (const float*)d_in[4];
    const float* b1        = (const float*)d_in[5];
    const float* W2        = (const float*)d_in[6];
    const float* b2        = (const float*)d_in[7];
    const float* Wc1       = (const float*)d_in[8];
    const float* bc1       = (const float*)d_in[9];
    const float* Wc2       = (const float*)d_in[10];
    const float* bc2       = (const float*)d_in[11];
    const float* alpha     = (const float*)d_in[12];
    const float* ln_g      = (const float*)d_in[13];
    const float* ln_b      = (const float*)d_in[14];
    const float* head_w    = (const float*)d_in[15];
    float* out = (float*)d_out;

    cudaFuncSetAttribute(evolve_mma, cudaFuncAttributeMaxDynamicSharedMemorySize, SMEM_TOTAL);

    prep_kernel<<<1, 1024>>>(c_states, Wc1, bc1, Wc2, bc2, W1, b1, alpha);
    pack_frag<<<160, 256>>>(W1, W2, head_w);
    evolve_mma<<<GRID_SZ, 256, SMEM_TOTAL>>>(tokens, embed, pos_embed, b2, ln_g, ln_b, out);
}

// round 16
// speedup vs baseline: 1.2738x; 1.0006x over previous
#include <cuda_runtime.h>
#include <cuda_bf16.h>
#include <math.h>

// CellularAutomatonDecoder via mma.sync m16n8k16 bf16 (base-target tensor cores).
// B=2048, T=32, D=128, V=256, 8 evolve steps.
// R16: fused hi/lo weight pass — each logical GEMM is ONE pass holding both
// W_hi and W_lo fragment sets; every loaded A_hi fragment feeds 2 HMMAs.
// A-LDSM -33%, pass count halved. Weights via LDG.128 from fragment-ordered
// gmem (L2-resident), pipelined 1 k-group ahead, chained across passes.
// acc2 stashed to smem between h-halves. Wave-balanced grid (592 = 4x148).

typedef unsigned int u32;

// ------------------------- global scratch -------------------------
// 20 tiles x 2048 uint4 (32KB each), fragment-ordered:
//   tile t, index ((nb*4 + kp)*32 + lane) -> uint4 {b0(ks=2kp), b1(2kp), b0(2kp+1), b1(2kp+1)}
//   n = nb*8 + lane/4, k0 = kp*32 + (lane%4)*2.
// t: 0..11 = W1(j*4 + h*2 + hl); 12..15 = W2(h*2+hl); 16..19 = head(h*2+hl).
__device__ __align__(16) uint4 g_wfrag[20 * 2048];
__device__ float g_const_bias[256];
__device__ float g_alpha_sig;

// ------------------------- helpers -------------------------
__device__ __forceinline__ u32 smem_u32(const void* p){
    u32 a; asm("{ .reg .u64 t; cvta.to.shared.u64 t, %1; cvt.u32.u64 %0, t; }" : "=r"(a) : "l"(p));
    return a;
}
__device__ __forceinline__ void ldmx4(u32 addr, u32& r0, u32& r1, u32& r2, u32& r3){
    asm volatile("ldmatrix.sync.aligned.m8n8.x4.shared.b16 {%0,%1,%2,%3}, [%4];"
        : "=r"(r0), "=r"(r1), "=r"(r2), "=r"(r3) : "r"(addr));
}
__device__ __forceinline__ void hmma(float* d, u32 a0, u32 a1, u32 a2, u32 a3, u32 b0, u32 b1){
    asm volatile("mma.sync.aligned.m16n8k16.row.col.f32.bf16.bf16.f32 "
        "{%0,%1,%2,%3},{%4,%5,%6,%7},{%8,%9},{%0,%1,%2,%3};"
        : "+f"(d[0]), "+f"(d[1]), "+f"(d[2]), "+f"(d[3])
        : "r"(a0), "r"(a1), "r"(a2), "r"(a3), "r"(b0), "r"(b1));
}
// fast gelu/tanh (abs err <= ~2e-7; tolerance margin ~1e-4)
__device__ __forceinline__ float erf_appx(float x){
    const float ax = fabsf(x);
    const float t  = __fdividef(1.0f, fmaf(0.3275911f, ax, 1.0f));
    float p = fmaf(1.061405429f, t, -1.453152027f);
    p = fmaf(p, t, 1.421413741f);
    p = fmaf(p, t, -0.284496736f);
    p = fmaf(p, t, 0.254829592f);
    const float r = 1.0f - (p * t) * __expf(-ax * ax);
    return copysignf(r, x);
}
__device__ __forceinline__ float gelu_fast(float x){
    return 0.5f * x * (1.0f + erf_appx(x * 0.70710678118654752440f));
}
__device__ __forceinline__ float tanh_fast(float x){
    const float e = __expf(-2.0f * fabsf(x));
    const float r = __fdividef(1.0f - e, 1.0f + e);
    return copysignf(r, x);
}
__device__ __forceinline__ float gelu_exact(float x){
    return 0.5f * x * (1.0f + erff(x * 0.70710678118654752440f));
}
__device__ __forceinline__ __nv_bfloat162 split_hi2(float v0, float v1, __nv_bfloat162& lo){
    __nv_bfloat16 h0 = __float2bfloat16_rn(v0);
    __nv_bfloat16 h1 = __float2bfloat16_rn(v1);
    lo = __halves2bfloat162(__float2bfloat16_rn(v0 - __bfloat162float(h0)),
                            __float2bfloat16_rn(v1 - __bfloat162float(h1)));
    return __halves2bfloat162(h0, h1);
}

// Pair schedule (66 fused passes). p in [0,64): step=p>>3, u=p&7, h=u>>2, v=u&3;
// v<3 -> W1 j=v pair; v==3 -> W2 pair. p in [64,66): head pair (p-64 = h).
__device__ __forceinline__ void pair_ptr(int p, const uint4*& ph, const uint4*& pl){
    if (p >= 66) p = 65;
    int t;
    if (p < 64){
        const int u = p & 7, h = u >> 2, v = u & 3;
        t = (v < 3) ? (v*4 + h*2) : (12 + h*2);
    } else {
        t = 16 + (p - 64)*2;
    }
    ph = g_wfrag + t*2048;
    pl = ph + 2048;
}

// Fused pass: acc += A_hi@W_hi + A_lo@W_hi + A_hi@W_lo over warp's [16*ns]m x 32n tile.
// Both weight fragment sets live in regs; each A_hi fragment feeds 2 HMMAs.
// Prefetches the NEXT pass's pair at kp==3 (bqh/bql chained across passes).
__device__ __forceinline__ void mma_passf(u32 abase, u32 dlo,
        const uint4* __restrict__ wh, const uint4* __restrict__ wl,
        const uint4* __restrict__ wnh, const uint4* __restrict__ wnl,
        uint4* bqh, uint4* bql, float (*acc)[4],
        int lane, int warpM, int warpN, int dj, int ns, int wofs)
{
    u32 arow[4];
    #pragma unroll
    for (int i = 0; i < 4; ++i){
        const int m = warpM*(16*ns) + i*16 + (lane & 15);
        const int mr = (m & ~31) | ((m + dj) & 31);
        arow[i] = abase + mr*272 + ((lane >> 4) << 4);
    }
    const uint4* wph = wh  + wofs;
    const uint4* wpl = wl  + wofs;
    const uint4* wqh = wnh + wofs;
    const uint4* wql = wnl + wofs;
    #pragma unroll
    for (int kp = 0; kp < 4; ++kp){
        uint4 bnh[4], bnl[4];
        {
            const uint4* sh = (kp < 3) ? (wph + (kp+1)*32) : wqh;
            const uint4* sl = (kp < 3) ? (wpl + (kp+1)*32) : wql;
            #pragma unroll
            for (int j = 0; j < 4; ++j) { bnh[j] = __ldg(sh + j*128); bnl[j] = __ldg(sl + j*128); }
        }
        u32 a[4][4];
        // ---- even k-step (k = kp*32 .. +15) ----
        #pragma unroll
        for (int i = 0; i < 4; ++i) if (i < ns) ldmx4(arow[i] + kp*64, a[i][0],a[i][1],a[i][2],a[i][3]);
        #pragma unroll
        for (int i = 0; i < 4; ++i) if (i < ns)
            #pragma unroll
            for (int j = 0; j < 4; ++j)
                hmma(acc[i*4+j], a[i][0],a[i][1],a[i][2],a[i][3], bqh[j].x, bqh[j].y);
        #pragma unroll
        for (int i = 0; i < 4; ++i) if (i < ns)
            #pragma unroll
            for (int j = 0; j < 4; ++j)
                hmma(acc[i*4+j], a[i][0],a[i][1],a[i][2],a[i][3], bql[j].x, bql[j].y);
        #pragma unroll
        for (int i = 0; i < 4; ++i) if (i < ns) ldmx4(arow[i] + dlo + kp*64, a[i][0],a[i][1],a[i][2],a[i][3]);
        #pragma unroll
        for (int i = 0; i < 4; ++i) if (i < ns)
            #pragma unroll
            for (int j = 0; j < 4; ++j)
                hmma(acc[i*4+j], a[i][0],a[i][1],a[i][2],a[i][3], bqh[j].x, bqh[j].y);
        // ---- odd k-step (k = kp*32+16 .. +31) ----
        #pragma unroll
        for (int i = 0; i < 4; ++i) if (i < ns) ldmx4(arow[i] + kp*64 + 32, a[i][0],a[i][1],a[i][2],a[i][3]);
        #pragma unroll
        for (int i = 0; i < 4; ++i) if (i < ns)
            #pragma unroll
            for (int j = 0; j < 4; ++j)
                hmma(acc[i*4+j], a[i][0],a[i][1],a[i][2],a[i][3], bqh[j].z, bqh[j].w);
        #pragma unroll
        for (int i = 0; i < 4; ++i) if (i < ns)
            #pragma unroll
            for (int j = 0; j < 4; ++j)
                hmma(acc[i*4+j], a[i][0],a[i][1],a[i][2],a[i][3], bql[j].z, bql[j].w);
        #pragma unroll
        for (int i = 0; i < 4; ++i) if (i < ns) ldmx4(arow[i] + dlo + kp*64 + 32, a[i][0],a[i][1],a[i][2],a[i][3]);
        #pragma unroll
        for (int i = 0; i < 4; ++i) if (i < ns)
            #pragma unroll
            for (int j = 0; j < 4; ++j)
                hmma(acc[i*4+j], a[i][0],a[i][1],a[i][2],a[i][3], bqh[j].z, bqh[j].w);
        #pragma unroll
        for (int j = 0; j < 4; ++j) { bqh[j] = bnh[j]; bql[j] = bnl[j]; }
    }
}

// ------------------------- prep (const_bias, alpha) -------------------------
__global__ void __launch_bounds__(1024)
prep_kernel(const float* __restrict__ c_states,
            const float* __restrict__ Wc1,
            const float* __restrict__ bc1,
            const float* __restrict__ Wc2,
            const float* __restrict__ bc2,
            const float* __restrict__ W1,
            const float* __restrict__ b1,
            const float* __restrict__ alpha)
{
    __shared__ float cp[128];
    __shared__ float h1[256];
    __shared__ float rb[128];
    const int tid = threadIdx.x;
    if (tid < 128)
        cp[tid] = 0.25f * (c_states[tid] + c_states[128+tid] + c_states[256+tid] + c_states[384+tid]);
    __syncthreads();
    {
        const int n = tid >> 2, r = tid & 3;
        float s = 0.f;
        for (int d = r; d < 128; d += 4) s += cp[d] * __ldg(Wc1 + d*256 + n);
        s += __shfl_xor_sync(0xffffffffu, s, 1);
        s += __shfl_xor_sync(0xffffffffu, s, 2);
        if (r == 0) h1[n] = gelu_exact(s + bc1[n]);
    }
    __syncthreads();
    {
        const int n = tid >> 3, r = tid & 7;
        float s = 0.f;
        for (int k = r; k < 256; k += 8) s += h1[k] * __ldg(Wc2 + k*128 + n);
        s += __shfl_xor_sync(0xffffffffu, s, 1);
        s += __shfl_xor_sync(0xffffffffu, s, 2);
        s += __shfl_xor_sync(0xffffffffu, s, 4);
        if (r == 0) rb[n] = s + bc2[n];
    }
    __syncthreads();
    {
        const int n = tid >> 2, r = tid & 3;
        float s = 0.f;
        for (int d = r; d < 128; d += 4) s += rb[d] * __ldg(W1 + (384 + d)*256 + n);
        s += __shfl_xor_sync(0xffffffffu, s, 1);
        s += __shfl_xor_sync(0xffffffffu, s, 2);
        if (r == 0) g_const_bias[n] = s + b1[n];
    }
    if (tid == 0) g_alpha_sig = 1.0f / (1.0f + expf(-alpha[0]));
}

// ------------------ pack weights into mma B-fragment order ------------------
__global__ void pack_frag(const float* __restrict__ W1,
                          const float* __restrict__ W2,
                          const float* __restrict__ head_w)
{
    const int idx = blockIdx.x * 256 + threadIdx.x;   // 0..40959
    const int t = idx >> 11;
    const int c = idx & 2047;
    const int nb = c >> 7, kp = (c >> 5) & 3, lane = c & 31;
    const int n  = nb*8 + (lane >> 2);
    const int k0 = kp*32 + (lane & 3)*2;
    const int hl = t & 1;

    float v[8];
    #pragma unroll
    for (int q = 0; q < 4; ++q) {
        const int k = k0 + q*8;
        float a, b;
        if (t < 12) {
            const int j = t >> 2, h = (t >> 1) & 1;
            a = W1[(j*128 + k  )*256 + h*128 + n];
            b = W1[(j*128 + k+1)*256 + h*128 + n];
        } else if (t < 16) {
            const int h = (t - 12) >> 1;
            a = W2[(h*128 + k  )*128 + n];
            b = W2[(h*128 + k+1)*128 + n];
        } else {
            const int h = (t - 16) >> 1;
            a = head_w[(k  )*256 + h*128 + n];
            b = head_w[(k+1)*256 + h*128 + n];
        }
        v[q*2] = a; v[q*2+1] = b;
    }
    u32 u[4];
    #pragma unroll
    for (int q = 0; q < 4; ++q) {
        __nv_bfloat16 h0 = __float2bfloat16_rn(v[q*2]);
        __nv_bfloat16 h1 = __float2bfloat16_rn(v[q*2+1]);
        __nv_bfloat16 e0 = hl ? __float2bfloat16_rn(v[q*2]   - __bfloat162float(h0)) : h0;
        __nv_bfloat16 e1 = hl ? __float2bfloat16_rn(v[q*2+1] - __bfloat162float(h1)) : h1;
        __nv_bfloat162 p = __halves2bfloat162(e0, e1);
        u[q] = *(u32*)&p;
    }
    g_wfrag[idx] = make_uint4(u[0], u[1], u[2], u[3]);
}

// ------------------------- SMEM layout (bytes) -------------------------
#define OA_HI   0
#define OA_LO   34816
#define OH_HI   69632
#define OH_LO   104448
#define OCB     139264
#define OB2     140288
#define OLNG    140800
#define OLNB    141312
#define OSTASH  141824      /* 16 x 256 float4 = 64KB acc2 stash */
#define SMEM_TOTAL 207360
#define DLO_A   34816

// ---------------- wave-balanced grid dispatch constants ----------------
#define N_FULL   444
#define N_HALF   124
#define GRID_SZ  592

// ------------------------- main fused kernel (256 threads) -------------------
__global__ void __launch_bounds__(256, 1)
evolve_mma(const int*   __restrict__ tokens,
           const float* __restrict__ embed,
           const float* __restrict__ pos_embed,
           const float* __restrict__ b2,
           const float* __restrict__ ln_g,
           const float* __restrict__ ln_b,
           float*       __restrict__ out)
{
    extern __shared__ char smem[];
    const u32 sb  = smem_u32(smem);
    const int tid = threadIdx.x, lane = tid & 31, wid = tid >> 5;
    const int warpM = wid & 1, warpN = wid >> 1;   // 2 x 4 warp grid
    const int bid = blockIdx.x;

    // ---- wave-balanced dispatch ----
    int ns, seq0;
    if (bid < N_FULL)              { ns = 4; seq0 = bid * 4; }
    else if (bid < N_FULL + N_HALF){ ns = 2; seq0 = N_FULL*4 + (bid - N_FULL)*2; }
    else                           { ns = 1; seq0 = N_FULL*4 + N_HALF*2 + (bid - N_FULL - N_HALF); }
    const int rows = ns * 32;
    const int rowbase = seq0 * 32;

    const u32 SA_HI = sb + OA_HI;
    const u32 SH_HI = sb + OH_HI;
    float*  cb    = (float*)(smem + OCB);
    float*  b2s   = (float*)(smem + OB2);
    float*  lng   = (float*)(smem + OLNG);
    float*  lnb   = (float*)(smem + OLNB);
    float4* stash = (float4*)(smem + OSTASH);

    cb[tid] = g_const_bias[tid];
    if (tid < 128) { b2s[tid] = b2[tid]; lng[tid] = ln_g[tid]; lnb[tid] = ln_b[tid]; }

    // ---- init cells = embed[token] + pos_embed (bf16 hi/lo split) ----
    for (int idx = tid; idx < rows*2; idx += 256) {
        const int m = idx >> 1, kh = (idx & 1) * 64;
        const int g = rowbase + m;
        const int tok = __ldg(tokens + g);
        const float* e = embed + tok*128 + kh;
        const float* p = pos_embed + (m & 31)*128 + kh;
        char* hi = smem + OA_HI + m*272 + kh*2;
        char* lo = smem + OA_LO + m*272 + kh*2;
        #pragma unroll 8
        for (int q = 0; q < 64; q += 2) {
            __nv_bfloat162 l2;
            __nv_bfloat162 h2 = split_hi2(e[q] + p[q], e[q+1] + p[q+1], l2);
            *(__nv_bfloat162*)(hi + q*2) = h2;
            *(__nv_bfloat162*)(lo + q*2) = l2;
        }
    }

    const int wofs = warpN*512 + lane;   // uint4 units
    int pc = 0;
    uint4 bqh[4], bql[4];
    {
        const uint4 *p0h, *p0l;
        pair_ptr(0, p0h, p0l);
        #pragma unroll
        for (int j = 0; j < 4; ++j) {
            bqh[j] = __ldg(p0h + wofs + j*128);
            bql[j] = __ldg(p0l + wofs + j*128);
        }
    }
    __syncthreads();   // cells + params visible

#define PASSF(ABASE, DJ, ACC) do { \
        const uint4 *_ph, *_pl, *_nh, *_nl; \
        pair_ptr(pc, _ph, _pl); pair_ptr(pc+1, _nh, _nl); \
        mma_passf(ABASE, DLO_A, _ph, _pl, _nh, _nl, bqh, bql, ACC, \
                  lane, warpM, warpN, DJ, ns, wofs); ++pc; } while(0)

    const float aa = g_alpha_sig, om = 1.0f - aa;

    // ================= 8 evolution steps =================
    for (int step = 0; step < 8; ++step) {
        for (int h = 0; h < 2; ++h) {
            float pre[16][4];
            #pragma unroll
            for (int x = 0; x < 16; ++x) { pre[x][0]=0.f; pre[x][1]=0.f; pre[x][2]=0.f; pre[x][3]=0.f; }

            // ---- matmul1: pre = X @ (W1c|W1l|W1r)[:, h-half], roll via A rows ----
            PASSF(SA_HI, 0,  pre);
            PASSF(SA_HI, 31, pre);
            PASSF(SA_HI, 1,  pre);

            __syncthreads();   // all warps done reading H (previous matmul2)
            // ---- epilogue1: H = gelu(pre + cb), split to bf16 hi/lo ----
            #pragma unroll
            for (int i = 0; i < 4; ++i) if (i < ns) {
                #pragma unroll
                for (int j4 = 0; j4 < 4; ++j4) {
                    const int c = warpN*32 + j4*8 + (lane & 3)*2;
                    const float cb0 = cb[h*128 + c], cb1 = cb[h*128 + c + 1];
                    float* d = pre[i*4 + j4];
                    #pragma unroll
                    for (int rr = 0; rr < 2; ++rr) {
                        const int r = warpM*(16*ns) + i*16 + (lane >> 2) + rr*8;
                        __nv_bfloat162 l2;
                        __nv_bfloat162 h2 = split_hi2(gelu_fast(d[rr*2]   + cb0),
                                                      gelu_fast(d[rr*2+1] + cb1), l2);
                        *(__nv_bfloat162*)(smem + OH_HI + r*272 + c*2) = h2;
                        *(__nv_bfloat162*)(smem + OH_LO + r*272 + c*2) = l2;
                    }
                }
            }
            __syncthreads();   // H published

            // ---- matmul2: acc2 (+)= H @ W2[h-chunk]; stash between halves ----
            float acc2[16][4];
            if (h == 0) {
                #pragma unroll
                for (int x = 0; x < 16; ++x) { acc2[x][0]=0.f; acc2[x][1]=0.f; acc2[x][2]=0.f; acc2[x][3]=0.f; }
            } else {
                #pragma unroll
                for (int x = 0; x < 16; ++x) {
                    float4 v = stash[(x << 8) | tid];
                    acc2[x][0]=v.x; acc2[x][1]=v.y; acc2[x][2]=v.z; acc2[x][3]=v.w;
                }
            }
            PASSF(SH_HI, 0, acc2);

            if (h == 0) {
                #pragma unroll
                for (int x = 0; x < 16; ++x)
                    stash[(x << 8) | tid] = make_float4(acc2[x][0], acc2[x][1], acc2[x][2], acc2[x][3]);
            } else {
                // ---- epilogue2: cells = a*cells + (1-a)*tanh(acc2 + b2) ----
                #pragma unroll
                for (int i = 0; i < 4; ++i) if (i < ns) {
                    #pragma unroll
                    for (int j4 = 0; j4 < 4; ++j4) {
                        const int c = warpN*32 + j4*8 + (lane & 3)*2;
                        const float bb0 = b2s[c], bb1 = b2s[c + 1];
                        float* d = acc2[i*4 + j4];
                        #pragma unroll
                        for (int rr = 0; rr < 2; ++rr) {
                            const int r = warpM*(16*ns) + i*16 + (lane >> 2) + rr*8;
                            const u32 offs = r*272 + c*2;
                            __nv_bfloat162 oh = *(__nv_bfloat162*)(smem + OA_HI + offs);
                            __nv_bfloat162 ol = *(__nv_bfloat162*)(smem + OA_LO + offs);
                            const float o0 = __bfloat162float(oh.x) + __bfloat162float(ol.x);
                            const float o1 = __bfloat162float(oh.y) + __bfloat162float(ol.y);
                            const float v0 = aa*o0 + om*tanh_fast(d[rr*2]   + bb0);
                            const float v1 = aa*o1 + om*tanh_fast(d[rr*2+1] + bb1);
                            __nv_bfloat162 l2;
                            __nv_bfloat162 h2 = split_hi2(v0, v1, l2);
                            *(__nv_bfloat162*)(smem + OA_HI + offs) = h2;
                            *(__nv_bfloat162*)(smem + OA_LO + offs) = l2;
                        }
                    }
                }
            }
        } // h
        __syncthreads();   // A updates published for next step
    } // steps

    // ================= LayerNorm per row (D=128), in-place =================
    if (tid < rows) {
        char* hi = smem + OA_HI + tid*272;
        char* lo = smem + OA_LO + tid*272;
        float s = 0.f, ss = 0.f;
        #pragma unroll 8
        for (int k = 0; k < 128; k += 2) {
            __nv_bfloat162 vh = *(__nv_bfloat162*)(hi + k*2);
            __nv_bfloat162 vl = *(__nv_bfloat162*)(lo + k*2);
            const float v0 = __bfloat162float(vh.x) + __bfloat162float(vl.x);
            const float v1 = __bfloat162float(vh.y) + __bfloat162float(vl.y);
            s += v0 + v1; ss += v0*v0 + v1*v1;
        }
        const float mu  = s * 0.0078125f;
        const float var = ss * 0.0078125f - mu*mu;
        const float inv = rsqrtf(var + 1e-5f);
        #pragma unroll 8
        for (int k = 0; k < 128; k += 2) {
            __nv_bfloat162 vh = *(__nv_bfloat162*)(hi + k*2);
            __nv_bfloat162 vl = *(__nv_bfloat162*)(lo + k*2);
            const float v0 = ((__bfloat162float(vh.x) + __bfloat162float(vl.x)) - mu)*inv*lng[k]   + lnb[k];
            const float v1 = ((__bfloat162float(vh.y) + __bfloat162float(vl.y)) - mu)*inv*lng[k+1] + lnb[k+1];
            __nv_bfloat162 l2;
            __nv_bfloat162 h2 = split_hi2(v0, v1, l2);
            *(__nv_bfloat162*)(hi + k*2) = h2;
            *(__nv_bfloat162*)(lo + k*2) = l2;
        }
    }
    __syncthreads();   // LN results published

    // ================= head: out = cells @ head_w =================
    for (int h = 0; h < 2; ++h) {
        float hacc[16][4];
        #pragma unroll
        for (int x = 0; x < 16; ++x) { hacc[x][0]=0.f; hacc[x][1]=0.f; hacc[x][2]=0.f; hacc[x][3]=0.f; }
        PASSF(SA_HI, 0, hacc);
        #pragma unroll
        for (int i = 0; i < 4; ++i) if (i < ns) {
            #pragma unroll
            for (int j4 = 0; j4 < 4; ++j4) {
                const int c = warpN*32 + j4*8 + (lane & 3)*2;
                float* d = hacc[i*4 + j4];
                #pragma unroll
                for (int rr = 0; rr < 2; ++rr) {
                    const int r = warpM*(16*ns) + i*16 + (lane >> 2) + rr*8;
                    *(float2*)(out + (size_t)(rowbase + r)*256 + h*128 + c) =
                        make_float2(d[rr*2], d[rr*2+1]);
                }
            }
        }
    }
#undef PASSF
}

// ---------------------------------------------------------------------------
extern "C" void kernel_launch(void* const* d_in, const int* in_sizes, int n_in,
                              void* d_out, int out_size)
{
    const int*   tokens    = (const int*)  d_in[0];
    const float* c_states  = (const float*)d_in[1];
    const float* embed     = (const float*)d_in[2];
    const float* pos_embed = (const float*)d_in[3];
    const float* W1        = (const float*)d_in[4];
    const float* b1        = (const float*)d_in[5];
    const float* W2        = (const float*)d_in[6];
    const float* b2        = (const float*)d_in[7];
    const float* Wc1       = (const float*)d_in[8];
    const float* bc1       = (const float*)d_in[9];
    const float* Wc2       = (const float*)d_in[10];
    const float* bc2       = (const float*)d_in[11];
    const float* alpha     = (const float*)d_in[12];
    const float* ln_g      = (const float*)d_in[13];
    const float* ln_b      = (const float*)d_in[14];
    const float* head_w    = (const float*)d_in[15];
    float* out = (float*)d_out;

    cudaFuncSetAttribute(evolve_mma, cudaFuncAttributeMaxDynamicSharedMemorySize, SMEM_TOTAL);

    prep_kernel<<<1, 1024>>>(c_states, Wc1, bc1, Wc2, bc2, W1, b1, alpha);
    pack_frag<<<160, 256>>>(W1, W2, head_w);
    evolve_mma<<<GRID_SZ, 256, SMEM_TOTAL>>>(tokens, embed, pos_embed, b2, ln_g, ln_b, out);
}

// round 17
// speedup vs baseline: 1.3927x; 1.0934x over previous
#include <cuda_runtime.h>
#include <cuda_bf16.h>
#include <math.h>

// CellularAutomatonDecoder via mma.sync m16n8k16 bf16 (base-target tensor cores).
// B=2048, T=32, D=128, V=256, 8 evolve steps.
// R17: half-height CTAs (128 threads, 4 warps, 1-2 seqs) at 2 CTAs/SM -> two
// independent barrier domains per SM; one CTA's MMA overlaps the other's
// epilogue/barrier. Pass structure identical to R16 (fused hi/lo weight pass,
// LDG.128 fragment-ordered weights, chained prefetch). Wave-balanced grid:
// 1184 CTAs = 4 exact waves of 296 (864 x 2seq + 320 x 1seq = 2048 seqs).

typedef unsigned int u32;

// ------------------------- global scratch -------------------------
// 20 tiles x 2048 uint4 (32KB each), fragment-ordered:
//   tile t, index ((nb*4 + kp)*32 + lane) -> uint4 {b0(2kp), b1(2kp), b0(2kp+1), b1(2kp+1)}
//   n = nb*8 + lane/4, k0 = kp*32 + (lane%4)*2.
// t: 0..11 = W1(j*4 + h*2 + hl); 12..15 = W2(h*2+hl); 16..19 = head(h*2+hl).
__device__ __align__(16) uint4 g_wfrag[20 * 2048];
__device__ float g_const_bias[256];
__device__ float g_alpha_sig;

// ------------------------- helpers -------------------------
__device__ __forceinline__ u32 smem_u32(const void* p){
    u32 a; asm("{ .reg .u64 t; cvta.to.shared.u64 t, %1; cvt.u32.u64 %0, t; }" : "=r"(a) : "l"(p));
    return a;
}
__device__ __forceinline__ void ldmx4(u32 addr, u32& r0, u32& r1, u32& r2, u32& r3){
    asm volatile("ldmatrix.sync.aligned.m8n8.x4.shared.b16 {%0,%1,%2,%3}, [%4];"
        : "=r"(r0), "=r"(r1), "=r"(r2), "=r"(r3) : "r"(addr));
}
__device__ __forceinline__ void hmma(float* d, u32 a0, u32 a1, u32 a2, u32 a3, u32 b0, u32 b1){
    asm volatile("mma.sync.aligned.m16n8k16.row.col.f32.bf16.bf16.f32 "
        "{%0,%1,%2,%3},{%4,%5,%6,%7},{%8,%9},{%0,%1,%2,%3};"
        : "+f"(d[0]), "+f"(d[1]), "+f"(d[2]), "+f"(d[3])
        : "r"(a0), "r"(a1), "r"(a2), "r"(a3), "r"(b0), "r"(b1));
}
// fast gelu/tanh (abs err <= ~2e-7; tolerance margin ~1e-4)
__device__ __forceinline__ float erf_appx(float x){
    const float ax = fabsf(x);
    const float t  = __fdividef(1.0f, fmaf(0.3275911f, ax, 1.0f));
    float p = fmaf(1.061405429f, t, -1.453152027f);
    p = fmaf(p, t, 1.421413741f);
    p = fmaf(p, t, -0.284496736f);
    p = fmaf(p, t, 0.254829592f);
    const float r = 1.0f - (p * t) * __expf(-ax * ax);
    return copysignf(r, x);
}
__device__ __forceinline__ float gelu_fast(float x){
    return 0.5f * x * (1.0f + erf_appx(x * 0.70710678118654752440f));
}
__device__ __forceinline__ float tanh_fast(float x){
    const float e = __expf(-2.0f * fabsf(x));
    const float r = __fdividef(1.0f - e, 1.0f + e);
    return copysignf(r, x);
}
__device__ __forceinline__ float gelu_exact(float x){
    return 0.5f * x * (1.0f + erff(x * 0.70710678118654752440f));
}
__device__ __forceinline__ __nv_bfloat162 split_hi2(float v0, float v1, __nv_bfloat162& lo){
    __nv_bfloat16 h0 = __float2bfloat16_rn(v0);
    __nv_bfloat16 h1 = __float2bfloat16_rn(v1);
    lo = __halves2bfloat162(__float2bfloat16_rn(v0 - __bfloat162float(h0)),
                            __float2bfloat16_rn(v1 - __bfloat162float(h1)));
    return __halves2bfloat162(h0, h1);
}

// Pair schedule (66 fused passes). p in [0,64): u=p&7, h=u>>2, v=u&3;
// v<3 -> W1 j=v pair; v==3 -> W2 pair. p in [64,66): head pair (p-64 = h).
__device__ __forceinline__ void pair_ptr(int p, const uint4*& ph, const uint4*& pl){
    if (p >= 66) p = 65;
    int t;
    if (p < 64){
        const int u = p & 7, h = u >> 2, v = u & 3;
        t = (v < 3) ? (v*4 + h*2) : (12 + h*2);
    } else {
        t = 16 + (p - 64)*2;
    }
    ph = g_wfrag + t*2048;
    pl = ph + 2048;
}

// Fused pass: acc += A_hi@W_hi + A_lo@W_hi + A_hi@W_lo over warp's [16*mt]m x 32n tile.
// mt = active m-tiles (rows/16, uniform per CTA). Prefetches next pass's pair.
__device__ __forceinline__ void mma_passf(u32 abase, u32 dlo,
        const uint4* __restrict__ wh, const uint4* __restrict__ wl,
        const uint4* __restrict__ wnh, const uint4* __restrict__ wnl,
        uint4* bqh, uint4* bql, float (*acc)[4],
        int lane, int warpN, int dj, int mt, int wofs)
{
    u32 arow[4];
    #pragma unroll
    for (int i = 0; i < 4; ++i){
        const int m = i*16 + (lane & 15);
        const int mr = (m & ~31) | ((m + dj) & 31);
        arow[i] = abase + mr*272 + ((lane >> 4) << 4);
    }
    const uint4* wph = wh  + wofs;
    const uint4* wpl = wl  + wofs;
    const uint4* wqh = wnh + wofs;
    const uint4* wql = wnl + wofs;
    #pragma unroll
    for (int kp = 0; kp < 4; ++kp){
        uint4 bnh[4], bnl[4];
        {
            const uint4* sh = (kp < 3) ? (wph + (kp+1)*32) : wqh;
            const uint4* sl = (kp < 3) ? (wpl + (kp+1)*32) : wql;
            #pragma unroll
            for (int j = 0; j < 4; ++j) { bnh[j] = __ldg(sh + j*128); bnl[j] = __ldg(sl + j*128); }
        }
        u32 a[4][4];
        // ---- even k-step ----
        #pragma unroll
        for (int i = 0; i < 4; ++i) if (i < mt) ldmx4(arow[i] + kp*64, a[i][0],a[i][1],a[i][2],a[i][3]);
        #pragma unroll
        for (int i = 0; i < 4; ++i) if (i < mt)
            #pragma unroll
            for (int j = 0; j < 4; ++j)
                hmma(acc[i*4+j], a[i][0],a[i][1],a[i][2],a[i][3], bqh[j].x, bqh[j].y);
        #pragma unroll
        for (int i = 0; i < 4; ++i) if (i < mt)
            #pragma unroll
            for (int j = 0; j < 4; ++j)
                hmma(acc[i*4+j], a[i][0],a[i][1],a[i][2],a[i][3], bql[j].x, bql[j].y);
        #pragma unroll
        for (int i = 0; i < 4; ++i) if (i < mt) ldmx4(arow[i] + dlo + kp*64, a[i][0],a[i][1],a[i][2],a[i][3]);
        #pragma unroll
        for (int i = 0; i < 4; ++i) if (i < mt)
            #pragma unroll
            for (int j = 0; j < 4; ++j)
                hmma(acc[i*4+j], a[i][0],a[i][1],a[i][2],a[i][3], bqh[j].x, bqh[j].y);
        // ---- odd k-step ----
        #pragma unroll
        for (int i = 0; i < 4; ++i) if (i < mt) ldmx4(arow[i] + kp*64 + 32, a[i][0],a[i][1],a[i][2],a[i][3]);
        #pragma unroll
        for (int i = 0; i < 4; ++i) if (i < mt)
            #pragma unroll
            for (int j = 0; j < 4; ++j)
                hmma(acc[i*4+j], a[i][0],a[i][1],a[i][2],a[i][3], bqh[j].z, bqh[j].w);
        #pragma unroll
        for (int i = 0; i < 4; ++i) if (i < mt)
            #pragma unroll
            for (int j = 0; j < 4; ++j)
                hmma(acc[i*4+j], a[i][0],a[i][1],a[i][2],a[i][3], bql[j].z, bql[j].w);
        #pragma unroll
        for (int i = 0; i < 4; ++i) if (i < mt) ldmx4(arow[i] + dlo + kp*64 + 32, a[i][0],a[i][1],a[i][2],a[i][3]);
        #pragma unroll
        for (int i = 0; i < 4; ++i) if (i < mt)
            #pragma unroll
            for (int j = 0; j < 4; ++j)
                hmma(acc[i*4+j], a[i][0],a[i][1],a[i][2],a[i][3], bqh[j].z, bqh[j].w);
        #pragma unroll
        for (int j = 0; j < 4; ++j) { bqh[j] = bnh[j]; bql[j] = bnl[j]; }
    }
}

// ------------------------- prep (const_bias, alpha) -------------------------
__global__ void __launch_bounds__(1024)
prep_kernel(const float* __restrict__ c_states,
            const float* __restrict__ Wc1,
            const float* __restrict__ bc1,
            const float* __restrict__ Wc2,
            const float* __restrict__ bc2,
            const float* __restrict__ W1,
            const float* __restrict__ b1,
            const float* __restrict__ alpha)
{
    __shared__ float cp[128];
    __shared__ float h1[256];
    __shared__ float rb[128];
    const int tid = threadIdx.x;
    if (tid < 128)
        cp[tid] = 0.25f * (c_states[tid] + c_states[128+tid] + c_states[256+tid] + c_states[384+tid]);
    __syncthreads();
    {
        const int n = tid >> 2, r = tid & 3;
        float s = 0.f;
        for (int d = r; d < 128; d += 4) s += cp[d] * __ldg(Wc1 + d*256 + n);
        s += __shfl_xor_sync(0xffffffffu, s, 1);
        s += __shfl_xor_sync(0xffffffffu, s, 2);
        if (r == 0) h1[n] = gelu_exact(s + bc1[n]);
    }
    __syncthreads();
    {
        const int n = tid >> 3, r = tid & 7;
        float s = 0.f;
        for (int k = r; k < 256; k += 8) s += h1[k] * __ldg(Wc2 + k*128 + n);
        s += __shfl_xor_sync(0xffffffffu, s, 1);
        s += __shfl_xor_sync(0xffffffffu, s, 2);
        s += __shfl_xor_sync(0xffffffffu, s, 4);
        if (r == 0) rb[n] = s + bc2[n];
    }
    __syncthreads();
    {
        const int n = tid >> 2, r = tid & 3;
        float s = 0.f;
        for (int d = r; d < 128; d += 4) s += rb[d] * __ldg(W1 + (384 + d)*256 + n);
        s += __shfl_xor_sync(0xffffffffu, s, 1);
        s += __shfl_xor_sync(0xffffffffu, s, 2);
        if (r == 0) g_const_bias[n] = s + b1[n];
    }
    if (tid == 0) g_alpha_sig = 1.0f / (1.0f + expf(-alpha[0]));
}

// ------------------ pack weights into mma B-fragment order ------------------
__global__ void pack_frag(const float* __restrict__ W1,
                          const float* __restrict__ W2,
                          const float* __restrict__ head_w)
{
    const int idx = blockIdx.x * 256 + threadIdx.x;   // 0..40959
    const int t = idx >> 11;
    const int c = idx & 2047;
    const int nb = c >> 7, kp = (c >> 5) & 3, lane = c & 31;
    const int n  = nb*8 + (lane >> 2);
    const int k0 = kp*32 + (lane & 3)*2;
    const int hl = t & 1;

    float v[8];
    #pragma unroll
    for (int q = 0; q < 4; ++q) {
        const int k = k0 + q*8;
        float a, b;
        if (t < 12) {
            const int j = t >> 2, h = (t >> 1) & 1;
            a = W1[(j*128 + k  )*256 + h*128 + n];
            b = W1[(j*128 + k+1)*256 + h*128 + n];
        } else if (t < 16) {
            const int h = (t - 12) >> 1;
            a = W2[(h*128 + k  )*128 + n];
            b = W2[(h*128 + k+1)*128 + n];
        } else {
            const int h = (t - 16) >> 1;
            a = head_w[(k  )*256 + h*128 + n];
            b = head_w[(k+1)*256 + h*128 + n];
        }
        v[q*2] = a; v[q*2+1] = b;
    }
    u32 u[4];
    #pragma unroll
    for (int q = 0; q < 4; ++q) {
        __nv_bfloat16 h0 = __float2bfloat16_rn(v[q*2]);
        __nv_bfloat16 h1 = __float2bfloat16_rn(v[q*2+1]);
        __nv_bfloat16 e0 = hl ? __float2bfloat16_rn(v[q*2]   - __bfloat162float(h0)) : h0;
        __nv_bfloat16 e1 = hl ? __float2bfloat16_rn(v[q*2+1] - __bfloat162float(h1)) : h1;
        __nv_bfloat162 p = __halves2bfloat162(e0, e1);
        u[q] = *(u32*)&p;
    }
    g_wfrag[idx] = make_uint4(u[0], u[1], u[2], u[3]);
}

// ------------------------- SMEM layout (bytes), 64-row CTA -------------------
// A/H tiles: rows stride 272 B, 64 rows = 17408 B each
#define OA_HI   0
#define OA_LO   17408
#define OH_HI   34816
#define OH_LO   52224
#define OCB     69632
#define OB2     70656
#define OLNG    71168
#define OLNB    71680
#define OSTASH  72192       /* 16 x 128 float4 = 32KB acc2 stash */
#define SMEM_TOTAL 104960
#define DLO_A   17408

// ---------------- wave-balanced grid dispatch constants ----------------
#define N_TWO    864    /* CTAs with 2 seqs */
#define GRID_SZ  1184   /* + 320 CTAs with 1 seq = 2048 seqs; 4 x 296 waves */

// ------------------- main fused kernel (128 threads, 2 CTAs/SM) --------------
__global__ void __launch_bounds__(128, 2)
evolve_mma(const int*   __restrict__ tokens,
           const float* __restrict__ embed,
           const float* __restrict__ pos_embed,
           const float* __restrict__ b2,
           const float* __restrict__ ln_g,
           const float* __restrict__ ln_b,
           float*       __restrict__ out)
{
    extern __shared__ char smem[];
    const u32 sb  = smem_u32(smem);
    const int tid = threadIdx.x, lane = tid & 31, warpN = tid >> 5;  // 4 warps over N
    const int bid = blockIdx.x;

    // ---- wave-balanced dispatch ----
    int nseq, seq0;
    if (bid < N_TWO) { nseq = 2; seq0 = bid * 2; }
    else             { nseq = 1; seq0 = N_TWO*2 + (bid - N_TWO); }
    const int rows = nseq * 32;
    const int mt   = nseq * 2;          // active 16-row m-tiles
    const int rowbase = seq0 * 32;

    const u32 SA_HI = sb + OA_HI;
    const u32 SH_HI = sb + OH_HI;
    float*  cb    = (float*)(smem + OCB);
    float*  b2s   = (float*)(smem + OB2);
    float*  lng   = (float*)(smem + OLNG);
    float*  lnb   = (float*)(smem + OLNB);
    float4* stash = (float4*)(smem + OSTASH);

    cb[tid] = g_const_bias[tid];
    cb[tid + 128] = g_const_bias[tid + 128];
    b2s[tid] = b2[tid]; lng[tid] = ln_g[tid]; lnb[tid] = ln_b[tid];

    // ---- init cells = embed[token] + pos_embed (bf16 hi/lo split) ----
    for (int idx = tid; idx < rows*2; idx += 128) {
        const int m = idx >> 1, kh = (idx & 1) * 64;
        const int g = rowbase + m;
        const int tok = __ldg(tokens + g);
        const float* e = embed + tok*128 + kh;
        const float* p = pos_embed + (m & 31)*128 + kh;
        char* hi = smem + OA_HI + m*272 + kh*2;
        char* lo = smem + OA_LO + m*272 + kh*2;
        #pragma unroll 8
        for (int q = 0; q < 64; q += 2) {
            __nv_bfloat162 l2;
            __nv_bfloat162 h2 = split_hi2(e[q] + p[q], e[q+1] + p[q+1], l2);
            *(__nv_bfloat162*)(hi + q*2) = h2;
            *(__nv_bfloat162*)(lo + q*2) = l2;
        }
    }

    const int wofs = warpN*512 + lane;   // uint4 units
    int pc = 0;
    uint4 bqh[4], bql[4];
    {
        const uint4 *p0h, *p0l;
        pair_ptr(0, p0h, p0l);
        #pragma unroll
        for (int j = 0; j < 4; ++j) {
            bqh[j] = __ldg(p0h + wofs + j*128);
            bql[j] = __ldg(p0l + wofs + j*128);
        }
    }
    __syncthreads();   // cells + params visible

#define PASSF(ABASE, DJ, ACC) do { \
        const uint4 *_ph, *_pl, *_nh, *_nl; \
        pair_ptr(pc, _ph, _pl); pair_ptr(pc+1, _nh, _nl); \
        mma_passf(ABASE, DLO_A, _ph, _pl, _nh, _nl, bqh, bql, ACC, \
                  lane, warpN, DJ, mt, wofs); ++pc; } while(0)

    const float aa = g_alpha_sig, om = 1.0f - aa;

    // ================= 8 evolution steps =================
    for (int step = 0; step < 8; ++step) {
        for (int h = 0; h < 2; ++h) {
            float pre[16][4];
            #pragma unroll
            for (int x = 0; x < 16; ++x) { pre[x][0]=0.f; pre[x][1]=0.f; pre[x][2]=0.f; pre[x][3]=0.f; }

            // ---- matmul1: pre = X @ (W1c|W1l|W1r)[:, h-half], roll via A rows ----
            PASSF(SA_HI, 0,  pre);
            PASSF(SA_HI, 31, pre);
            PASSF(SA_HI, 1,  pre);

            __syncthreads();   // all warps done reading H (previous matmul2)
            // ---- epilogue1: H = gelu(pre + cb), split to bf16 hi/lo ----
            #pragma unroll
            for (int i = 0; i < 4; ++i) if (i < mt) {
                #pragma unroll
                for (int j4 = 0; j4 < 4; ++j4) {
                    const int c = warpN*32 + j4*8 + (lane & 3)*2;
                    const float cb0 = cb[h*128 + c], cb1 = cb[h*128 + c + 1];
                    float* d = pre[i*4 + j4];
                    #pragma unroll
                    for (int rr = 0; rr < 2; ++rr) {
                        const int r = i*16 + (lane >> 2) + rr*8;
                        __nv_bfloat162 l2;
                        __nv_bfloat162 h2 = split_hi2(gelu_fast(d[rr*2]   + cb0),
                                                      gelu_fast(d[rr*2+1] + cb1), l2);
                        *(__nv_bfloat162*)(smem + OH_HI + r*272 + c*2) = h2;
                        *(__nv_bfloat162*)(smem + OH_LO + r*272 + c*2) = l2;
                    }
                }
            }
            __syncthreads();   // H published

            // ---- matmul2: acc2 (+)= H @ W2[h-chunk]; stash between halves ----
            float acc2[16][4];
            if (h == 0) {
                #pragma unroll
                for (int x = 0; x < 16; ++x) { acc2[x][0]=0.f; acc2[x][1]=0.f; acc2[x][2]=0.f; acc2[x][3]=0.f; }
            } else {
                #pragma unroll
                for (int x = 0; x < 16; ++x) {
                    float4 v = stash[(x << 7) | tid];
                    acc2[x][0]=v.x; acc2[x][1]=v.y; acc2[x][2]=v.z; acc2[x][3]=v.w;
                }
            }
            PASSF(SH_HI, 0, acc2);

            if (h == 0) {
                #pragma unroll
                for (int x = 0; x < 16; ++x)
                    stash[(x << 7) | tid] = make_float4(acc2[x][0], acc2[x][1], acc2[x][2], acc2[x][3]);
            } else {
                // ---- epilogue2: cells = a*cells + (1-a)*tanh(acc2 + b2) ----
                #pragma unroll
                for (int i = 0; i < 4; ++i) if (i < mt) {
                    #pragma unroll
                    for (int j4 = 0; j4 < 4; ++j4) {
                        const int c = warpN*32 + j4*8 + (lane & 3)*2;
                        const float bb0 = b2s[c], bb1 = b2s[c + 1];
                        float* d = acc2[i*4 + j4];
                        #pragma unroll
                        for (int rr = 0; rr < 2; ++rr) {
                            const int r = i*16 + (lane >> 2) + rr*8;
                            const u32 offs = r*272 + c*2;
                            __nv_bfloat162 oh = *(__nv_bfloat162*)(smem + OA_HI + offs);
                            __nv_bfloat162 ol = *(__nv_bfloat162*)(smem + OA_LO + offs);
                            const float o0 = __bfloat162float(oh.x) + __bfloat162float(ol.x);
                            const float o1 = __bfloat162float(oh.y) + __bfloat162float(ol.y);
                            const float v0 = aa*o0 + om*tanh_fast(d[rr*2]   + bb0);
                            const float v1 = aa*o1 + om*tanh_fast(d[rr*2+1] + bb1);
                            __nv_bfloat162 l2;
                            __nv_bfloat162 h2 = split_hi2(v0, v1, l2);
                            *(__nv_bfloat162*)(smem + OA_HI + offs) = h2;
                            *(__nv_bfloat162*)(smem + OA_LO + offs) = l2;
                        }
                    }
                }
            }
        } // h
        __syncthreads();   // A updates published for next step
    } // steps

    // ================= LayerNorm per row (D=128), in-place =================
    if (tid < rows) {
        char* hi = smem + OA_HI + tid*272;
        char* lo = smem + OA_LO + tid*272;
        float s = 0.f, ss = 0.f;
        #pragma unroll 8
        for (int k = 0; k < 128; k += 2) {
            __nv_bfloat162 vh = *(__nv_bfloat162*)(hi + k*2);
            __nv_bfloat162 vl = *(__nv_bfloat162*)(lo + k*2);
            const float v0 = __bfloat162float(vh.x) + __bfloat162float(vl.x);
            const float v1 = __bfloat162float(vh.y) + __bfloat162float(vl.y);
            s += v0 + v1; ss += v0*v0 + v1*v1;
        }
        const float mu  = s * 0.0078125f;
        const float var = ss * 0.0078125f - mu*mu;
        const float inv = rsqrtf(var + 1e-5f);
        #pragma unroll 8
        for (int k = 0; k < 128; k += 2) {
            __nv_bfloat162 vh = *(__nv_bfloat162*)(hi + k*2);
            __nv_bfloat162 vl = *(__nv_bfloat162*)(lo + k*2);
            const float v0 = ((__bfloat162float(vh.x) + __bfloat162float(vl.x)) - mu)*inv*lng[k]   + lnb[k];
            const float v1 = ((__bfloat162float(vh.y) + __bfloat162float(vl.y)) - mu)*inv*lng[k+1] + lnb[k+1];
            __nv_bfloat162 l2;
            __nv_bfloat162 h2 = split_hi2(v0, v1, l2);
            *(__nv_bfloat162*)(hi + k*2) = h2;
            *(__nv_bfloat162*)(lo + k*2) = l2;
        }
    }
    __syncthreads();   // LN results published

    // ================= head: out = cells @ head_w =================
    for (int h = 0; h < 2; ++h) {
        float hacc[16][4];
        #pragma unroll
        for (int x = 0; x < 16; ++x) { hacc[x][0]=0.f; hacc[x][1]=0.f; hacc[x][2]=0.f; hacc[x][3]=0.f; }
        PASSF(SA_HI, 0, hacc);
        #pragma unroll
        for (int i = 0; i < 4; ++i) if (i < mt) {
            #pragma unroll
            for (int j4 = 0; j4 < 4; ++j4) {
                const int c = warpN*32 + j4*8 + (lane & 3)*2;
                float* d = hacc[i*4 + j4];
                #pragma unroll
                for (int rr = 0; rr < 2; ++rr) {
                    const int r = i*16 + (lane >> 2) + rr*8;
                    *(float2*)(out + (size_t)(rowbase + r)*256 + h*128 + c) =
                        make_float2(d[rr*2], d[rr*2+1]);
                }
            }
        }
    }
#undef PASSF
}

// ---------------------------------------------------------------------------
extern "C" void kernel_launch(void* const* d_in, const int* in_sizes, int n_in,
                              void* d_out, int out_size)
{
    const int*   tokens    = (const int*)  d_in[0];
    const float* c_states  = (const float*)d_in[1];
    const float* embed     = (const float*)d_in[2];
    const float* pos_embed = (const float*)d_in[3];
    const float* W1        = (const float*)d_in[4];
    const float* b1        = (const float*)d_in[5];
    const float* W2        = (const float*)d_in[6];
    const float* b2        = (const float*)d_in[7];
    const float* Wc1       = (const float*)d_in[8];
    const float* bc1       = (const float*)d_in[9];
    const float* Wc2       = (const float*)d_in[10];
    const float* bc2       = (const float*)d_in[11];
    const float* alpha     = (const float*)d_in[12];
    const float* ln_g      = (const float*)d_in[13];
    const float* ln_b      = (const float*)d_in[14];
    const float* head_w    = (const float*)d_in[15];
    float* out = (float*)d_out;

    cudaFuncSetAttribute(evolve_mma, cudaFuncAttributeMaxDynamicSharedMemorySize, SMEM_TOTAL);

    prep_kernel<<<1, 1024>>>(c_states, Wc1, bc1, Wc2, bc2, W1, b1, alpha);
    pack_frag<<<160, 256>>>(W1, W2, head_w);
    evolve_mma<<<GRID_SZ, 128, SMEM_TOTAL>>>(tokens, embed, pos_embed, b2, ln_g, ln_b, out);
}